// round 1
// baseline (speedup 1.0000x reference)
#include <cuda_runtime.h>
#include <math.h>

#define B 2
#define DIM 384
#define HEADS 8
#define C 48
#define IMG 128
#define HW (IMG*IMG)        // 16384
#define SPLITS 16
#define CHUNK (HW/SPLITS)   // 1024

// ---------------- scratch (static device globals; no allocations) ----------
__device__ float g_qc[B*DIM*HW];        // dwconv(q)
__device__ float g_kc[B*DIM*HW];        // dwconv(k)
__device__ float g_vc[B*DIM*HW];        // dwconv(v)
__device__ float g_ssq[B*DIM];          // sum of squares per (b, channel) of qc
__device__ float g_ssk[B*DIM];          // sum of squares per (b, channel) of kc
__device__ float g_G[B*HEADS*C*C];      // unnormalized q@k^T
__device__ float g_A[B*HEADS*C*C];      // combined weighted-softmax attention
__device__ float g_M[B*DIM*DIM];        // Wproj @ blockdiag(A)

// ---------------- zero accumulators ----------------------------------------
__global__ void zero_k() {
    int i = blockIdx.x * blockDim.x + threadIdx.x;
    if (i < B*DIM) { g_ssq[i] = 0.f; g_ssk[i] = 0.f; }
    if (i < B*HEADS*C*C) g_G[i] = 0.f;
}

// ---------------- depthwise 3x3 conv (SAME), optional sum-of-squares -------
// which: 0 -> qc (+ssq), 1 -> kc (+ssk), 2 -> vc (no norm)
__global__ void dwconv_k(const float* __restrict__ in,
                         const float* __restrict__ w, int which)
{
    float* out = (which == 0) ? g_qc : (which == 1) ? g_kc : g_vc;
    float* ssq = (which == 0) ? g_ssq : (which == 1) ? g_ssk : nullptr;

    int bc = blockIdx.y;                 // 0 .. B*DIM-1
    int c  = bc % DIM;
    int p  = blockIdx.x * blockDim.x + threadIdx.x;   // 0 .. HW-1
    int y  = p >> 7;
    int x  = p & 127;

    const float* ip = in + (size_t)bc * HW;
    float wv[9];
#pragma unroll
    for (int i = 0; i < 9; i++) wv[i] = w[c*9 + i];

    float acc = 0.f;
#pragma unroll
    for (int dy = -1; dy <= 1; dy++) {
        int yy = y + dy;
        if ((unsigned)yy < (unsigned)IMG) {
#pragma unroll
            for (int dx = -1; dx <= 1; dx++) {
                int xx = x + dx;
                if ((unsigned)xx < (unsigned)IMG)
                    acc += ip[yy*IMG + xx] * wv[(dy+1)*3 + (dx+1)];
            }
        }
    }
    out[(size_t)bc * HW + p] = acc;

    if (which < 2) {
        __shared__ float red[256];
        red[threadIdx.x] = acc * acc;
        __syncthreads();
#pragma unroll
        for (int off = 128; off > 0; off >>= 1) {
            if (threadIdx.x < off) red[threadIdx.x] += red[threadIdx.x + off];
            __syncthreads();
        }
        if (threadIdx.x == 0) atomicAdd(&ssq[bc], red[0]);
    }
}

// ---------------- G = Q @ K^T (unnormalized), split-K with atomics ---------
// grid: (SPLITS, B*HEADS), block 256 (16x16), each thread 3x3 outputs
__global__ void __launch_bounds__(256) gemm_qk()
{
    __shared__ float Qs[C][33];
    __shared__ float Ks[C][33];
    int bh = blockIdx.y;
    int b  = bh >> 3, hd = bh & 7;
    size_t base = ((size_t)(b*DIM + hd*C)) * HW + (size_t)blockIdx.x * CHUNK;

    int tid = threadIdx.x;
    int ty = tid >> 4, tx = tid & 15;

    float acc[3][3];
#pragma unroll
    for (int i = 0; i < 3; i++)
#pragma unroll
        for (int j = 0; j < 3; j++) acc[i][j] = 0.f;

    for (int kt = 0; kt < CHUNK; kt += 32) {
        for (int i = tid; i < C*32; i += 256) {
            int r = i >> 5, kk = i & 31;
            size_t off = base + (size_t)r * HW + kt + kk;
            Qs[r][kk] = g_qc[off];
            Ks[r][kk] = g_kc[off];
        }
        __syncthreads();
#pragma unroll 8
        for (int kk = 0; kk < 32; kk++) {
            float qv[3], kv[3];
#pragma unroll
            for (int i = 0; i < 3; i++) { qv[i] = Qs[ty + 16*i][kk]; kv[i] = Ks[tx + 16*i][kk]; }
#pragma unroll
            for (int i = 0; i < 3; i++)
#pragma unroll
                for (int j = 0; j < 3; j++) acc[i][j] += qv[i] * kv[j];
        }
        __syncthreads();
    }
    float* Gb = &g_G[bh * C * C];
#pragma unroll
    for (int i = 0; i < 3; i++)
#pragma unroll
        for (int j = 0; j < 3; j++)
            atomicAdd(&Gb[(ty + 16*i)*C + (tx + 16*j)], acc[i][j]);
}

// ---------------- per-row: normalize, top-k masked softmax, combine --------
// one thread per (b, head, c) row of 48 values
__global__ void rowcomb(const float* __restrict__ temp, const float* __restrict__ attw)
{
    int row = blockIdx.x * blockDim.x + threadIdx.x;
    if (row >= B*HEADS*C) return;
    int b   = row / (HEADS*C);
    int rem = row % (HEADS*C);
    int hd  = rem / C, c = rem % C;

    float inq = 1.f / fmaxf(sqrtf(g_ssq[b*DIM + hd*C + c]), 1e-12f);
    float t   = temp[hd];
    const float* Gr = &g_G[((b*HEADS + hd)*C + c) * C];

    float vals[C], s[C];
#pragma unroll 4
    for (int d = 0; d < C; d++) {
        float ink = 1.f / fmaxf(sqrtf(g_ssk[b*DIM + hd*C + d]), 1e-12f);
        float v = Gr[d] * inq * ink * t;
        vals[d] = v;
        s[d] = v;
    }
    // insertion sort descending
    for (int i = 1; i < C; i++) {
        float key = s[i]; int j = i - 1;
        while (j >= 0 && s[j] < key) { s[j+1] = s[j]; j--; }
        s[j+1] = key;
    }
    float m = s[0];
    const int kl[4] = {C/2, C*2/3, C*3/4, C*4/5};   // 24, 32, 36, 38
    float denom[4];
    float run = 0.f; int ki = 0;
    for (int r = 0; r < C; r++) {
        run += expf(s[r] - m);
        if (ki < 4 && r + 1 == kl[ki]) { denom[ki] = run; ki++; }
    }
    float th[4], wd[4];
#pragma unroll
    for (int i = 0; i < 4; i++) { th[i] = s[kl[i]-1]; wd[i] = attw[i] / denom[i]; }

    float* Ar = &g_A[((b*HEADS + hd)*C + c) * C];
#pragma unroll 4
    for (int d = 0; d < C; d++) {
        float e = expf(vals[d] - m);
        float cf = 0.f;
#pragma unroll
        for (int i = 0; i < 4; i++) if (vals[d] >= th[i]) cf += wd[i];
        Ar[d] = e * cf;
    }
}

// ---------------- M[b] = Wproj @ blockdiag(A[b])  (2 x 384 x 384) ----------
__global__ void buildM(const float* __restrict__ wproj)
{
    int idx = blockIdx.x * blockDim.x + threadIdx.x;
    if (idx >= B*DIM*DIM) return;
    int b  = idx / (DIM*DIM);
    int r  = idx % (DIM*DIM);
    int co = r / DIM;
    int g  = r % DIM;          // global in-channel (head*48 + dl)
    int hh = g / C, dl = g % C;

    const float* wp = wproj + co*DIM + hh*C;                 // wproj[co, hh*48 + cc]
    const float* Ac = &g_A[((b*HEADS + hh)*C) * C + dl];     // A[b,hh,cc,dl], stride C
    float acc = 0.f;
#pragma unroll
    for (int cc = 0; cc < C; cc++) acc += wp[cc] * Ac[cc*C];
    g_M[idx] = acc;
}

// ---------------- final fused GEMM: y[b] = M[b] (384x384) @ Vc[b] (384xHW) --
#define BCO 128
#define BP  128
#define TK  8
__global__ void __launch_bounds__(256) finalgemm(float* __restrict__ y)
{
    __shared__ float Ms[TK][BCO];
    __shared__ float Vs[TK][BP];
    int b   = blockIdx.z;
    int co0 = blockIdx.y * BCO;
    int p0  = blockIdx.x * BP;
    const float* Mb = g_M + (size_t)b * DIM * DIM;
    const float* Vb = g_vc + (size_t)b * DIM * HW;

    int tid = threadIdx.x;
    int tco = (tid >> 4) * 8;   // 16 co-groups x 8
    int tp  = (tid & 15) * 8;   // 16 p-groups  x 8

    float acc[8][8];
#pragma unroll
    for (int i = 0; i < 8; i++)
#pragma unroll
        for (int j = 0; j < 8; j++) acc[i][j] = 0.f;

    for (int k0 = 0; k0 < DIM; k0 += TK) {
        // Ms[kk][cc] = M[b, co0+cc, k0+kk]
        for (int i = tid; i < TK*BCO; i += 256) {
            int cc = i >> 3, kk = i & 7;
            Ms[kk][cc] = Mb[(size_t)(co0 + cc) * DIM + k0 + kk];
        }
        // Vs[kk][pp] = Vc[b, k0+kk, p0+pp]   (coalesced)
        for (int i = tid; i < TK*BP; i += 256) {
            int kk = i >> 7, pp = i & 127;
            Vs[kk][pp] = Vb[(size_t)(k0 + kk) * HW + p0 + pp];
        }
        __syncthreads();
#pragma unroll
        for (int kk = 0; kk < TK; kk++) {
            float a[8], vv[8];
            *(float4*)&a[0]  = *(const float4*)&Ms[kk][tco];
            *(float4*)&a[4]  = *(const float4*)&Ms[kk][tco + 4];
            *(float4*)&vv[0] = *(const float4*)&Vs[kk][tp];
            *(float4*)&vv[4] = *(const float4*)&Vs[kk][tp + 4];
#pragma unroll
            for (int i = 0; i < 8; i++)
#pragma unroll
                for (int j = 0; j < 8; j++) acc[i][j] += a[i] * vv[j];
        }
        __syncthreads();
    }
#pragma unroll
    for (int i = 0; i < 8; i++) {
        size_t rowoff = ((size_t)b*DIM + co0 + tco + i) * HW + p0 + tp;
        float4 v0 = make_float4(acc[i][0], acc[i][1], acc[i][2], acc[i][3]);
        float4 v1 = make_float4(acc[i][4], acc[i][5], acc[i][6], acc[i][7]);
        *(float4*)&y[rowoff]     = v0;
        *(float4*)&y[rowoff + 4] = v1;
    }
}

// ---------------- launch ----------------------------------------------------
extern "C" void kernel_launch(void* const* d_in, const int* in_sizes, int n_in,
                              void* d_out, int out_size)
{
    const float* k_fea = (const float*)d_in[0];
    const float* v_fea = (const float*)d_in[1];
    const float* q_fea = (const float*)d_in[2];
    const float* wq    = (const float*)d_in[3];
    const float* wk    = (const float*)d_in[4];
    const float* wv    = (const float*)d_in[5];
    const float* wproj = (const float*)d_in[6];
    const float* temp  = (const float*)d_in[7];
    const float* attw  = (const float*)d_in[8];
    float* y = (float*)d_out;

    zero_k<<<(B*HEADS*C*C + 255)/256, 256>>>();

    dim3 gconv(HW/256, B*DIM);
    dwconv_k<<<gconv, 256>>>(q_fea, wq, 0);
    dwconv_k<<<gconv, 256>>>(k_fea, wk, 1);
    dwconv_k<<<gconv, 256>>>(v_fea, wv, 2);

    gemm_qk<<<dim3(SPLITS, B*HEADS), 256>>>();

    rowcomb<<<(B*HEADS*C + 255)/256, 256>>>(temp, attw);

    buildM<<<(B*DIM*DIM + 255)/256, 256>>>(wproj);

    finalgemm<<<dim3(HW/BP, DIM/BCO, B), 256>>>(y);
}

// round 3
// speedup vs baseline: 3.8757x; 3.8757x over previous
#include <cuda_runtime.h>
#include <cuda_bf16.h>
#include <cstdint>
#include <math.h>

#define B 2
#define DIM 384
#define HEADS 8
#define C 48
#define IMG 128
#define HW (IMG*IMG)        // 16384
#define QK_SPLITS 32
#define QK_CHUNK (HW/QK_SPLITS)   // 512

// ---------------- scratch (static device globals; no allocations) ----------
__device__ __align__(16) float g_qc[B*DIM*HW];
__device__ __align__(16) float g_kc[B*DIM*HW];
__device__ __align__(16) __nv_bfloat16 g_vhi[B*DIM*HW];   // dwconv(v) hi, [b][ch][p]
__device__ __align__(16) __nv_bfloat16 g_vlo[B*DIM*HW];   // dwconv(v) lo
__device__ float g_ssq[B*DIM];
__device__ float g_ssk[B*DIM];
__device__ float g_G[B*HEADS*C*C];
__device__ float g_A[B*HEADS*C*C];
__device__ __align__(16) __nv_bfloat16 g_Mhi[B*DIM*DIM];  // [b][co][k] hi
__device__ __align__(16) __nv_bfloat16 g_Mlo[B*DIM*DIM];  // [b][co][k] lo

// ================= PTX helpers (compute_103-safe: sm_80+ features) =========
__device__ __forceinline__ uint32_t smem_u32(const void* p) {
    uint32_t a;
    asm("{ .reg .u64 t; cvta.to.shared.u64 t, %1; cvt.u32.u64 %0, t; }"
        : "=r"(a) : "l"(p));
    return a;
}
__device__ __forceinline__ void cpa16(uint32_t saddr, const void* g) {
    asm volatile("cp.async.cg.shared.global [%0], [%1], 16;"
                 :: "r"(saddr), "l"(g) : "memory");
}
#define CP_COMMIT() asm volatile("cp.async.commit_group;" ::: "memory")
#define CP_WAIT1()  asm volatile("cp.async.wait_group 1;" ::: "memory")

__device__ __forceinline__ void ldmA(uint32_t* a, uint32_t addr) {
    asm volatile("ldmatrix.sync.aligned.m8n8.x4.shared.b16 {%0,%1,%2,%3}, [%4];"
        : "=r"(a[0]), "=r"(a[1]), "=r"(a[2]), "=r"(a[3]) : "r"(addr));
}
__device__ __forceinline__ void ldmBt(uint32_t* bf, uint32_t addr) {
    asm volatile("ldmatrix.sync.aligned.m8n8.x2.trans.shared.b16 {%0,%1}, [%2];"
        : "=r"(bf[0]), "=r"(bf[1]) : "r"(addr));
}
__device__ __forceinline__ void mma16816(float* c, const uint32_t* a, const uint32_t* bf) {
    asm volatile("mma.sync.aligned.m16n8k16.row.col.f32.bf16.bf16.f32 "
        "{%0,%1,%2,%3}, {%4,%5,%6,%7}, {%8,%9}, {%0,%1,%2,%3};"
        : "+f"(c[0]), "+f"(c[1]), "+f"(c[2]), "+f"(c[3])
        : "r"(a[0]), "r"(a[1]), "r"(a[2]), "r"(a[3]), "r"(bf[0]), "r"(bf[1]));
}

// ---------------- zero accumulators ----------------------------------------
__global__ void zero_k() {
    int i = blockIdx.x * blockDim.x + threadIdx.x;
    if (i < B*DIM) { g_ssq[i] = 0.f; g_ssk[i] = 0.f; }
    if (i < B*HEADS*C*C) g_G[i] = 0.f;
}

// ---------------- depthwise 3x3 conv, 4 outputs/thread ---------------------
__device__ __forceinline__ uint32_t pack_bf2(float a, float b) {
    __nv_bfloat162 t(__float2bfloat16(a), __float2bfloat16(b));
    return *reinterpret_cast<uint32_t*>(&t);
}
__global__ void __launch_bounds__(256) dwconv_k(const float* __restrict__ in,
                                                const float* __restrict__ w, int which)
{
    int bc = blockIdx.y;
    int c  = bc % DIM;
    int tid = threadIdx.x;
    int p4 = blockIdx.x * 1024 + tid * 4;
    int y  = p4 >> 7;
    int x  = p4 & 127;

    const float* ip = in + (size_t)bc * HW;
    float wv[9];
#pragma unroll
    for (int i = 0; i < 9; i++) wv[i] = w[c*9 + i];

    float a0 = 0.f, a1 = 0.f, a2 = 0.f, a3 = 0.f;
#pragma unroll
    for (int dy = -1; dy <= 1; dy++) {
        int yy = y + dy;
        if ((unsigned)yy < (unsigned)IMG) {
            const float* row = ip + yy*IMG + x;
            float l = (x > 0) ? row[-1] : 0.f;
            float4 m = *(const float4*)row;
            float r = (x + 4 < IMG) ? row[4] : 0.f;
            float w0 = wv[(dy+1)*3], w1 = wv[(dy+1)*3+1], w2 = wv[(dy+1)*3+2];
            a0 += w0*l   + w1*m.x + w2*m.y;
            a1 += w0*m.x + w1*m.y + w2*m.z;
            a2 += w0*m.y + w1*m.z + w2*m.w;
            a3 += w0*m.z + w1*m.w + w2*r;
        }
    }

    if (which == 2) {
        float h0 = __bfloat162float(__float2bfloat16(a0));
        float h1 = __bfloat162float(__float2bfloat16(a1));
        float h2 = __bfloat162float(__float2bfloat16(a2));
        float h3 = __bfloat162float(__float2bfloat16(a3));
        uint2 uh, ul;
        uh.x = pack_bf2(a0, a1); uh.y = pack_bf2(a2, a3);
        ul.x = pack_bf2(a0 - h0, a1 - h1); ul.y = pack_bf2(a2 - h2, a3 - h3);
        *(uint2*)&g_vhi[(size_t)bc*HW + p4] = uh;
        *(uint2*)&g_vlo[(size_t)bc*HW + p4] = ul;
    } else {
        float* out = (which == 0) ? g_qc : g_kc;
        *(float4*)&out[(size_t)bc*HW + p4] = make_float4(a0, a1, a2, a3);
        float* ssq = (which == 0) ? g_ssq : g_ssk;
        __shared__ float red[256];
        red[tid] = a0*a0 + a1*a1 + a2*a2 + a3*a3;
        __syncthreads();
#pragma unroll
        for (int off = 128; off > 0; off >>= 1) {
            if (tid < off) red[tid] += red[tid + off];
            __syncthreads();
        }
        if (tid == 0) atomicAdd(&ssq[bc], red[0]);
    }
}

// ---------------- G = Q @ K^T, 64 threads, 6x6 per thread ------------------
__global__ void __launch_bounds__(64) gemm_qk()
{
    __shared__ float Qs[C][33];
    __shared__ float Ks[C][33];
    int bh = blockIdx.y;
    int b  = bh >> 3, hd = bh & 7;
    size_t base = ((size_t)(b*DIM + hd*C)) * HW + (size_t)blockIdx.x * QK_CHUNK;

    int tid = threadIdx.x;
    int ty = tid >> 3, tx = tid & 7;

    float acc[6][6];
#pragma unroll
    for (int i = 0; i < 6; i++)
#pragma unroll
        for (int j = 0; j < 6; j++) acc[i][j] = 0.f;

    for (int kt = 0; kt < QK_CHUNK; kt += 32) {
        for (int i = tid; i < C*32; i += 64) {
            int r = i >> 5, kk = i & 31;
            size_t off = base + (size_t)r * HW + kt + kk;
            Qs[r][kk] = g_qc[off];
            Ks[r][kk] = g_kc[off];
        }
        __syncthreads();
#pragma unroll 4
        for (int kk = 0; kk < 32; kk++) {
            float qv[6], kv[6];
#pragma unroll
            for (int i = 0; i < 6; i++) { qv[i] = Qs[ty*6 + i][kk]; kv[i] = Ks[tx*6 + i][kk]; }
#pragma unroll
            for (int i = 0; i < 6; i++)
#pragma unroll
                for (int j = 0; j < 6; j++) acc[i][j] += qv[i] * kv[j];
        }
        __syncthreads();
    }
    float* Gb = &g_G[bh * C * C];
#pragma unroll
    for (int i = 0; i < 6; i++)
#pragma unroll
        for (int j = 0; j < 6; j++)
            atomicAdd(&Gb[(ty*6 + i)*C + (tx*6 + j)], acc[i][j]);
}

// ---------------- per-row normalize + top-k masked softmax + combine -------
__global__ void rowcomb(const float* __restrict__ temp, const float* __restrict__ attw)
{
    int row = blockIdx.x * blockDim.x + threadIdx.x;
    if (row >= B*HEADS*C) return;
    int b   = row / (HEADS*C);
    int rem = row % (HEADS*C);
    int hd  = rem / C, c = rem % C;

    float inq = 1.f / fmaxf(sqrtf(g_ssq[b*DIM + hd*C + c]), 1e-12f);
    float t   = temp[hd];
    const float* Gr = &g_G[((b*HEADS + hd)*C + c) * C];

    float vals[C], s[C];
#pragma unroll 4
    for (int d = 0; d < C; d++) {
        float ink = 1.f / fmaxf(sqrtf(g_ssk[b*DIM + hd*C + d]), 1e-12f);
        float v = Gr[d] * inq * ink * t;
        vals[d] = v;
        s[d] = v;
    }
    for (int i = 1; i < C; i++) {
        float key = s[i]; int j = i - 1;
        while (j >= 0 && s[j] < key) { s[j+1] = s[j]; j--; }
        s[j+1] = key;
    }
    float m = s[0];
    const int kl[4] = {C/2, C*2/3, C*3/4, C*4/5};
    float denom[4];
    float run = 0.f; int ki = 0;
    for (int r = 0; r < C; r++) {
        run += expf(s[r] - m);
        if (ki < 4 && r + 1 == kl[ki]) { denom[ki] = run; ki++; }
    }
    float th[4], wd[4];
#pragma unroll
    for (int i = 0; i < 4; i++) { th[i] = s[kl[i]-1]; wd[i] = attw[i] / denom[i]; }

    float* Ar = &g_A[((b*HEADS + hd)*C + c) * C];
#pragma unroll 4
    for (int d = 0; d < C; d++) {
        float e = expf(vals[d] - m);
        float cf = 0.f;
#pragma unroll
        for (int i = 0; i < 4; i++) if (vals[d] >= th[i]) cf += wd[i];
        Ar[d] = e * cf;
    }
}

// ---------------- M[b] = Wproj @ blockdiag(A[b]), split to bf16 hi/lo ------
__global__ void buildM(const float* __restrict__ wproj)
{
    int idx = blockIdx.x * blockDim.x + threadIdx.x;
    if (idx >= B*DIM*DIM) return;
    int b  = idx / (DIM*DIM);
    int r  = idx % (DIM*DIM);
    int co = r / DIM;
    int g  = r % DIM;
    int hh = g / C, dl = g % C;

    const float* wp = wproj + co*DIM + hh*C;
    const float* Ac = &g_A[((b*HEADS + hh)*C) * C + dl];
    float acc = 0.f;
#pragma unroll
    for (int cc = 0; cc < C; cc++) acc += wp[cc] * Ac[cc*C];
    __nv_bfloat16 hi = __float2bfloat16(acc);
    g_Mhi[idx] = hi;
    g_Mlo[idx] = __float2bfloat16(acc - __bfloat162float(hi));
}

// ---------------- final GEMM via ldmatrix + mma.sync bf16 split-precision --
// y[b](384 x 16384) = M[b](384x384) @ V[b](384x16384)
// CTA tile: 128(m=co) x 128(n=p), K chunks of 32, 2-stage cp.async pipeline.
// 8 warps: warp_m = wid&1 (2x64), warp_n = wid>>1 (4x32). Warp tile 64x32.
#define AST_B 80      // A smem row stride bytes (32 bf16 + 8 pad)
#define BST_B 272     // B smem row stride bytes (128 bf16 + 8 pad)
#define A_STG (128*AST_B)   // 10240 per stage
#define B_STG (32*BST_B)    // 8704 per stage
#define OFF_AHI 0
#define OFF_ALO (2*A_STG)              // 20480
#define OFF_BHI (4*A_STG)              // 40960
#define OFF_BLO (4*A_STG + 2*B_STG)    // 58368
#define FG_SMEM (4*A_STG + 4*B_STG)    // 75776
#define NKC 12        // 384/32

__global__ void __launch_bounds__(256) finalgemm(float* __restrict__ y)
{
    extern __shared__ char smem[];
    uint32_t sb = smem_u32(smem);
    int tid = threadIdx.x, wid = tid >> 5, lid = tid & 31;
    int b   = blockIdx.z;
    int co0 = blockIdx.y * 128;
    int p0  = blockIdx.x * 128;
    int wm  = (wid & 1) * 64;     // warp m offset in CTA tile
    int wn  = (wid >> 1) * 32;    // warp n offset

    const __nv_bfloat16* Mh = g_Mhi + (size_t)b * DIM * DIM;
    const __nv_bfloat16* Ml = g_Mlo + (size_t)b * DIM * DIM;
    const __nv_bfloat16* Vh = g_vhi + (size_t)b * DIM * HW;
    const __nv_bfloat16* Vl = g_vlo + (size_t)b * DIM * HW;

    float acc[4][4][4];
#pragma unroll
    for (int mt = 0; mt < 4; mt++)
#pragma unroll
        for (int nt = 0; nt < 4; nt++)
#pragma unroll
            for (int i = 0; i < 4; i++) acc[mt][nt][i] = 0.f;

    // ---- async tile loader: chunk kc into stage st ----
    auto load_chunk = [&](int kc, int st) {
        int k0 = kc * 32;
        // A: 128 rows x 32 bf16 (4 x 16B per row), hi + lo
#pragma unroll
        for (int i = tid; i < 512; i += 256) {
            int r = i >> 2, cc = i & 3;
            size_t go = (size_t)(co0 + r)*DIM + k0 + cc*8;
            uint32_t so = r*AST_B + cc*16;
            cpa16(sb + OFF_AHI + st*A_STG + so, Mh + go);
            cpa16(sb + OFF_ALO + st*A_STG + so, Ml + go);
        }
        // B: 32 rows (k) x 128 bf16 (p) (16 x 16B per row), hi + lo
#pragma unroll
        for (int i = tid; i < 512; i += 256) {
            int r = i >> 4, cc = i & 15;
            size_t go = (size_t)(k0 + r)*HW + p0 + cc*8;
            uint32_t so = r*BST_B + cc*16;
            cpa16(sb + OFF_BHI + st*B_STG + so, Vh + go);
            cpa16(sb + OFF_BLO + st*B_STG + so, Vl + go);
        }
    };

    load_chunk(0, 0);
    CP_COMMIT();

    for (int kc = 0; kc < NKC; kc++) {
        int st = kc & 1;
        if (kc + 1 < NKC) load_chunk(kc + 1, (kc + 1) & 1);
        CP_COMMIT();
        CP_WAIT1();
        __syncthreads();

        // per-lane ldmatrix base addresses for this stage
        uint32_t aAh = sb + OFF_AHI + st*A_STG + (wm + (lid & 15))*AST_B + (lid >> 4)*16;
        uint32_t aAl = aAh + (OFF_ALO - OFF_AHI);
        uint32_t aBh = sb + OFF_BHI + st*B_STG + (lid & 15)*BST_B + wn*2;
        uint32_t aBl = aBh + (OFF_BLO - OFF_BHI);

#pragma unroll
        for (int ks = 0; ks < 2; ks++) {            // two k16 steps in chunk
            uint32_t Ah[4][4], Al[4][4], Bh[4][2], Bl[4][2];
#pragma unroll
            for (int mt = 0; mt < 4; mt++) {
                ldmA(Ah[mt], aAh + mt*16*AST_B + ks*32);
                ldmA(Al[mt], aAl + mt*16*AST_B + ks*32);
            }
#pragma unroll
            for (int nt = 0; nt < 4; nt++) {
                ldmBt(Bh[nt], aBh + ks*16*BST_B + nt*16);
                ldmBt(Bl[nt], aBl + ks*16*BST_B + nt*16);
            }
#pragma unroll
            for (int mt = 0; mt < 4; mt++)
#pragma unroll
                for (int nt = 0; nt < 4; nt++) {
                    mma16816(acc[mt][nt], Ah[mt], Bh[nt]);
                    mma16816(acc[mt][nt], Ah[mt], Bl[nt]);
                    mma16816(acc[mt][nt], Al[mt], Bh[nt]);
                }
        }
        __syncthreads();
    }

    // ---- epilogue: direct global write (float2 per fragment half) ----
    int group = lid >> 2, tg = lid & 3;
#pragma unroll
    for (int mt = 0; mt < 4; mt++) {
        int row0 = co0 + wm + mt*16 + group;
#pragma unroll
        for (int nt = 0; nt < 4; nt++) {
            int col = p0 + wn + nt*8 + tg*2;
            size_t o0 = ((size_t)(b*DIM + row0))     * HW + col;
            size_t o1 = ((size_t)(b*DIM + row0 + 8)) * HW + col;
            *(float2*)&y[o0] = make_float2(acc[mt][nt][0], acc[mt][nt][1]);
            *(float2*)&y[o1] = make_float2(acc[mt][nt][2], acc[mt][nt][3]);
        }
    }
}

// ---------------- launch ----------------------------------------------------
extern "C" void kernel_launch(void* const* d_in, const int* in_sizes, int n_in,
                              void* d_out, int out_size)
{
    const float* k_fea = (const float*)d_in[0];
    const float* v_fea = (const float*)d_in[1];
    const float* q_fea = (const float*)d_in[2];
    const float* wq    = (const float*)d_in[3];
    const float* wk    = (const float*)d_in[4];
    const float* wv    = (const float*)d_in[5];
    const float* wproj = (const float*)d_in[6];
    const float* temp  = (const float*)d_in[7];
    const float* attw  = (const float*)d_in[8];
    float* y = (float*)d_out;

    static int smem_set = 0;
    if (!smem_set) {
        cudaFuncSetAttribute(finalgemm, cudaFuncAttributeMaxDynamicSharedMemorySize,
                             FG_SMEM);
        smem_set = 1;
    }

    zero_k<<<(B*HEADS*C*C + 255)/256, 256>>>();

    dim3 gconv(HW/1024, B*DIM);
    dwconv_k<<<gconv, 256>>>(q_fea, wq, 0);
    dwconv_k<<<gconv, 256>>>(k_fea, wk, 1);
    dwconv_k<<<gconv, 256>>>(v_fea, wv, 2);

    gemm_qk<<<dim3(QK_SPLITS, B*HEADS), 64>>>();

    rowcomb<<<(B*HEADS*C + 255)/256, 256>>>(temp, attw);

    buildM<<<(B*DIM*DIM + 255)/256, 256>>>(wproj);

    finalgemm<<<dim3(HW/128, DIM/128, B), 256, FG_SMEM>>>(y);
}

// round 4
// speedup vs baseline: 5.6658x; 1.4619x over previous
#include <cuda_runtime.h>
#include <cuda_bf16.h>
#include <cstdint>
#include <math.h>

#define B 2
#define DIM 384
#define HEADS 8
#define C 48
#define IMG 128
#define HW (IMG*IMG)        // 16384
#define QK_SPLITS 64
#define QK_CHUNK (HW/QK_SPLITS)   // 256

// ---------------- scratch (static device globals; no allocations) ----------
__device__ __align__(16) float g_qc[B*DIM*HW];
__device__ __align__(16) float g_kc[B*DIM*HW];
__device__ __align__(16) __nv_bfloat16 g_vhi[B*DIM*HW];   // dwconv(v) hi, [b][ch][p]
__device__ __align__(16) __nv_bfloat16 g_vlo[B*DIM*HW];   // dwconv(v) lo
__device__ float g_ssq[B*DIM];
__device__ float g_ssk[B*DIM];
__device__ float g_G[B*HEADS*C*C];
__device__ float g_A[B*HEADS*C*C];
__device__ __align__(16) __nv_bfloat16 g_Mhi[B*DIM*DIM];  // [b][co][k] hi
__device__ __align__(16) __nv_bfloat16 g_Mlo[B*DIM*DIM];  // [b][co][k] lo

// ================= PTX helpers (compute_103-safe: sm_80+ features) =========
__device__ __forceinline__ uint32_t smem_u32(const void* p) {
    uint32_t a;
    asm("{ .reg .u64 t; cvta.to.shared.u64 t, %1; cvt.u32.u64 %0, t; }"
        : "=r"(a) : "l"(p));
    return a;
}
__device__ __forceinline__ void cpa16(uint32_t saddr, const void* g) {
    asm volatile("cp.async.cg.shared.global [%0], [%1], 16;"
                 :: "r"(saddr), "l"(g) : "memory");
}
#define CP_COMMIT() asm volatile("cp.async.commit_group;" ::: "memory")
#define CP_WAIT1()  asm volatile("cp.async.wait_group 1;" ::: "memory")

__device__ __forceinline__ void ldmA(uint32_t* a, uint32_t addr) {
    asm volatile("ldmatrix.sync.aligned.m8n8.x4.shared.b16 {%0,%1,%2,%3}, [%4];"
        : "=r"(a[0]), "=r"(a[1]), "=r"(a[2]), "=r"(a[3]) : "r"(addr));
}
__device__ __forceinline__ void ldmBt(uint32_t* bf, uint32_t addr) {
    asm volatile("ldmatrix.sync.aligned.m8n8.x2.trans.shared.b16 {%0,%1}, [%2];"
        : "=r"(bf[0]), "=r"(bf[1]) : "r"(addr));
}
__device__ __forceinline__ void mma16816(float* c, const uint32_t* a, const uint32_t* bf) {
    asm volatile("mma.sync.aligned.m16n8k16.row.col.f32.bf16.bf16.f32 "
        "{%0,%1,%2,%3}, {%4,%5,%6,%7}, {%8,%9}, {%0,%1,%2,%3};"
        : "+f"(c[0]), "+f"(c[1]), "+f"(c[2]), "+f"(c[3])
        : "r"(a[0]), "r"(a[1]), "r"(a[2]), "r"(a[3]), "r"(bf[0]), "r"(bf[1]));
}

// ---------------- zero accumulators ----------------------------------------
__global__ void zero_k() {
    int i = blockIdx.x * blockDim.x + threadIdx.x;
    if (i < B*DIM) { g_ssq[i] = 0.f; g_ssk[i] = 0.f; }
    if (i < B*HEADS*C*C) g_G[i] = 0.f;
}

// ---------------- depthwise 3x3 conv, warp-per-row, shuffle halos ----------
__device__ __forceinline__ uint32_t pack_bf2(float a, float b) {
    __nv_bfloat162 t(__float2bfloat16(a), __float2bfloat16(b));
    return *reinterpret_cast<uint32_t*>(&t);
}
__global__ void __launch_bounds__(256) dwconv_k(const float* __restrict__ in,
                                                const float* __restrict__ w, int which)
{
    int bc  = blockIdx.y;
    int c   = bc % DIM;
    int wid = threadIdx.x >> 5, lid = threadIdx.x & 31;
    int y   = blockIdx.x * 8 + wid;   // one warp per image row
    int x   = lid * 4;

    const float* ip = in + (size_t)bc * HW;
    float wv[9];
#pragma unroll
    for (int i = 0; i < 9; i++) wv[i] = w[c*9 + i];

    float a0 = 0.f, a1 = 0.f, a2 = 0.f, a3 = 0.f;
#pragma unroll
    for (int dy = -1; dy <= 1; dy++) {
        int yy = y + dy;
        if ((unsigned)yy < (unsigned)IMG) {
            float4 m = *(const float4*)(ip + yy*IMG + x);
            float l = __shfl_up_sync(0xffffffffu, m.w, 1);
            float r = __shfl_down_sync(0xffffffffu, m.x, 1);
            if (lid == 0)  l = 0.f;
            if (lid == 31) r = 0.f;
            float w0 = wv[(dy+1)*3], w1 = wv[(dy+1)*3+1], w2 = wv[(dy+1)*3+2];
            a0 += w0*l   + w1*m.x + w2*m.y;
            a1 += w0*m.x + w1*m.y + w2*m.z;
            a2 += w0*m.y + w1*m.z + w2*m.w;
            a3 += w0*m.z + w1*m.w + w2*r;
        }
    }

    size_t po = (size_t)bc*HW + y*IMG + x;
    if (which == 2) {
        float h0 = __bfloat162float(__float2bfloat16(a0));
        float h1 = __bfloat162float(__float2bfloat16(a1));
        float h2 = __bfloat162float(__float2bfloat16(a2));
        float h3 = __bfloat162float(__float2bfloat16(a3));
        uint2 uh, ul;
        uh.x = pack_bf2(a0, a1); uh.y = pack_bf2(a2, a3);
        ul.x = pack_bf2(a0 - h0, a1 - h1); ul.y = pack_bf2(a2 - h2, a3 - h3);
        *(uint2*)&g_vhi[po] = uh;
        *(uint2*)&g_vlo[po] = ul;
    } else {
        float* out = (which == 0) ? g_qc : g_kc;
        *(float4*)&out[po] = make_float4(a0, a1, a2, a3);
        float* ssq = (which == 0) ? g_ssq : g_ssk;
        float s = a0*a0 + a1*a1 + a2*a2 + a3*a3;
#pragma unroll
        for (int off = 16; off > 0; off >>= 1)
            s += __shfl_xor_sync(0xffffffffu, s, off);
        __shared__ float red[8];
        if (lid == 0) red[wid] = s;
        __syncthreads();
        if (threadIdx.x == 0) {
            float tot = 0.f;
#pragma unroll
            for (int i = 0; i < 8; i++) tot += red[i];
            atomicAdd(&ssq[bc], tot);
        }
    }
}

// ---------------- G = Q @ K^T, 64 threads, 6x6 per thread ------------------
__global__ void __launch_bounds__(64) gemm_qk()
{
    __shared__ float Qs[C][33];
    __shared__ float Ks[C][33];
    int bh = blockIdx.y;
    int b  = bh >> 3, hd = bh & 7;
    size_t base = ((size_t)(b*DIM + hd*C)) * HW + (size_t)blockIdx.x * QK_CHUNK;

    int tid = threadIdx.x;
    int ty = tid >> 3, tx = tid & 7;

    float acc[6][6];
#pragma unroll
    for (int i = 0; i < 6; i++)
#pragma unroll
        for (int j = 0; j < 6; j++) acc[i][j] = 0.f;

    for (int kt = 0; kt < QK_CHUNK; kt += 32) {
        for (int i = tid; i < C*32; i += 64) {
            int r = i >> 5, kk = i & 31;
            size_t off = base + (size_t)r * HW + kt + kk;
            Qs[r][kk] = g_qc[off];
            Ks[r][kk] = g_kc[off];
        }
        __syncthreads();
#pragma unroll 4
        for (int kk = 0; kk < 32; kk++) {
            float qv[6], kv[6];
#pragma unroll
            for (int i = 0; i < 6; i++) { qv[i] = Qs[ty*6 + i][kk]; kv[i] = Ks[tx*6 + i][kk]; }
#pragma unroll
            for (int i = 0; i < 6; i++)
#pragma unroll
                for (int j = 0; j < 6; j++) acc[i][j] += qv[i] * kv[j];
        }
        __syncthreads();
    }
    float* Gb = &g_G[bh * C * C];
#pragma unroll
    for (int i = 0; i < 6; i++)
#pragma unroll
        for (int j = 0; j < 6; j++)
            atomicAdd(&Gb[(ty*6 + i)*C + (tx*6 + j)], acc[i][j]);
}

// ---------------- rowcomb: warp-per-row, rank-based (no sort, no spills) ---
// For each row of 48 attn values: L2-normalize, compute rank of each element,
// nested top-k softmax denominators via predicated warp reductions.
__global__ void __launch_bounds__(256) rowcomb(const float* __restrict__ temp,
                                               const float* __restrict__ attw)
{
    __shared__ float sv[8][48];
    int wid = threadIdx.x >> 5, lid = threadIdx.x & 31;
    int row = blockIdx.x * 8 + wid;          // 0 .. 767
    int b   = row / (HEADS*C);
    int rem = row % (HEADS*C);
    int hd  = rem / C, c = rem % C;

    float inq = 1.f / fmaxf(sqrtf(g_ssq[b*DIM + hd*C + c]), 1e-12f);
    float t   = temp[hd];
    const float* Gr = &g_G[((b*HEADS + hd)*C + c) * C];

    // compute scaled values: lane handles d=lid and (if lid<16) d=lid+32
    float v0, v1 = -1e30f;
    {
        float ink = 1.f / fmaxf(sqrtf(g_ssk[b*DIM + hd*C + lid]), 1e-12f);
        v0 = Gr[lid] * inq * ink * t;
        sv[wid][lid] = v0;
        if (lid < 16) {
            int d = lid + 32;
            float ink2 = 1.f / fmaxf(sqrtf(g_ssk[b*DIM + hd*C + d]), 1e-12f);
            v1 = Gr[d] * inq * ink2 * t;
            sv[wid][d] = v1;
        }
    }
    __syncwarp();

    // max over 48
    float m = fmaxf(v0, v1);
#pragma unroll
    for (int off = 16; off > 0; off >>= 1)
        m = fmaxf(m, __shfl_xor_sync(0xffffffffu, m, off));

    // ranks (stable ties by index, matching descending-stable sort / top_k)
    int r0 = 0, r1 = 0;
#pragma unroll 8
    for (int j = 0; j < C; j++) {
        float vj = sv[wid][j];
        r0 += (vj > v0) || (vj == v0 && j < lid);
        if (lid < 16) r1 += (vj > v1) || (vj == v1 && j < lid + 32);
    }
    float e0 = expf(v0 - m);
    float e1 = (lid < 16) ? expf(v1 - m) : 0.f;

    const int kl[4] = {C/2, C*2/3, C*3/4, C*4/5};   // 24, 32, 36, 38
    float ds[4];
#pragma unroll
    for (int i = 0; i < 4; i++)
        ds[i] = ((r0 < kl[i]) ? e0 : 0.f) + ((lid < 16 && r1 < kl[i]) ? e1 : 0.f);
#pragma unroll
    for (int off = 16; off > 0; off >>= 1) {
#pragma unroll
        for (int i = 0; i < 4; i++)
            ds[i] += __shfl_xor_sync(0xffffffffu, ds[i], off);
    }

    float cf0 = 0.f, cf1 = 0.f;
#pragma unroll
    for (int i = 0; i < 4; i++) {
        float wdi = attw[i] / ds[i];
        if (r0 < kl[i]) cf0 += wdi;
        if (r1 < kl[i]) cf1 += wdi;
    }

    float* Ar = &g_A[((b*HEADS + hd)*C + c) * C];
    Ar[lid] = e0 * cf0;
    if (lid < 16) Ar[lid + 32] = e1 * cf1;
}

// ---------------- M[b] = Wproj @ blockdiag(A[b]), split to bf16 hi/lo ------
__global__ void buildM(const float* __restrict__ wproj)
{
    int idx = blockIdx.x * blockDim.x + threadIdx.x;
    if (idx >= B*DIM*DIM) return;
    int b  = idx / (DIM*DIM);
    int r  = idx % (DIM*DIM);
    int co = r / DIM;
    int g  = r % DIM;
    int hh = g / C, dl = g % C;

    const float* wp = wproj + co*DIM + hh*C;
    const float* Ac = &g_A[((b*HEADS + hh)*C) * C + dl];
    float acc = 0.f;
#pragma unroll
    for (int cc = 0; cc < C; cc++) acc += wp[cc] * Ac[cc*C];
    __nv_bfloat16 hi = __float2bfloat16(acc);
    g_Mhi[idx] = hi;
    g_Mlo[idx] = __float2bfloat16(acc - __bfloat162float(hi));
}

// ---------------- final GEMM via ldmatrix + mma.sync bf16 split-precision --
#define AST_B 80
#define BST_B 272
#define A_STG (128*AST_B)
#define B_STG (32*BST_B)
#define OFF_AHI 0
#define OFF_ALO (2*A_STG)
#define OFF_BHI (4*A_STG)
#define OFF_BLO (4*A_STG + 2*B_STG)
#define FG_SMEM (4*A_STG + 4*B_STG)
#define NKC 12

__global__ void __launch_bounds__(256) finalgemm(float* __restrict__ y)
{
    extern __shared__ char smem[];
    uint32_t sb = smem_u32(smem);
    int tid = threadIdx.x, wid = tid >> 5, lid = tid & 31;
    int b   = blockIdx.z;
    int co0 = blockIdx.y * 128;
    int p0  = blockIdx.x * 128;
    int wm  = (wid & 1) * 64;
    int wn  = (wid >> 1) * 32;

    const __nv_bfloat16* Mh = g_Mhi + (size_t)b * DIM * DIM;
    const __nv_bfloat16* Ml = g_Mlo + (size_t)b * DIM * DIM;
    const __nv_bfloat16* Vh = g_vhi + (size_t)b * DIM * HW;
    const __nv_bfloat16* Vl = g_vlo + (size_t)b * DIM * HW;

    float acc[4][4][4];
#pragma unroll
    for (int mt = 0; mt < 4; mt++)
#pragma unroll
        for (int nt = 0; nt < 4; nt++)
#pragma unroll
            for (int i = 0; i < 4; i++) acc[mt][nt][i] = 0.f;

    auto load_chunk = [&](int kc, int st) {
        int k0 = kc * 32;
#pragma unroll
        for (int i = tid; i < 512; i += 256) {
            int r = i >> 2, cc = i & 3;
            size_t go = (size_t)(co0 + r)*DIM + k0 + cc*8;
            uint32_t so = r*AST_B + cc*16;
            cpa16(sb + OFF_AHI + st*A_STG + so, Mh + go);
            cpa16(sb + OFF_ALO + st*A_STG + so, Ml + go);
        }
#pragma unroll
        for (int i = tid; i < 512; i += 256) {
            int r = i >> 4, cc = i & 15;
            size_t go = (size_t)(k0 + r)*HW + p0 + cc*8;
            uint32_t so = r*BST_B + cc*16;
            cpa16(sb + OFF_BHI + st*B_STG + so, Vh + go);
            cpa16(sb + OFF_BLO + st*B_STG + so, Vl + go);
        }
    };

    load_chunk(0, 0);
    CP_COMMIT();

    for (int kc = 0; kc < NKC; kc++) {
        int st = kc & 1;
        if (kc + 1 < NKC) load_chunk(kc + 1, (kc + 1) & 1);
        CP_COMMIT();
        CP_WAIT1();
        __syncthreads();

        uint32_t aAh = sb + OFF_AHI + st*A_STG + (wm + (lid & 15))*AST_B + (lid >> 4)*16;
        uint32_t aAl = aAh + (OFF_ALO - OFF_AHI);
        uint32_t aBh = sb + OFF_BHI + st*B_STG + (lid & 15)*BST_B + wn*2;
        uint32_t aBl = aBh + (OFF_BLO - OFF_BHI);

#pragma unroll
        for (int ks = 0; ks < 2; ks++) {
            uint32_t Ah[4][4], Al[4][4], Bh[4][2], Bl[4][2];
#pragma unroll
            for (int mt = 0; mt < 4; mt++) {
                ldmA(Ah[mt], aAh + mt*16*AST_B + ks*32);
                ldmA(Al[mt], aAl + mt*16*AST_B + ks*32);
            }
#pragma unroll
            for (int nt = 0; nt < 4; nt++) {
                ldmBt(Bh[nt], aBh + ks*16*BST_B + nt*16);
                ldmBt(Bl[nt], aBl + ks*16*BST_B + nt*16);
            }
#pragma unroll
            for (int mt = 0; mt < 4; mt++)
#pragma unroll
                for (int nt = 0; nt < 4; nt++) {
                    mma16816(acc[mt][nt], Ah[mt], Bh[nt]);
                    mma16816(acc[mt][nt], Ah[mt], Bl[nt]);
                    mma16816(acc[mt][nt], Al[mt], Bh[nt]);
                }
        }
        __syncthreads();
    }

    int group = lid >> 2, tg = lid & 3;
#pragma unroll
    for (int mt = 0; mt < 4; mt++) {
        int row0 = co0 + wm + mt*16 + group;
#pragma unroll
        for (int nt = 0; nt < 4; nt++) {
            int col = p0 + wn + nt*8 + tg*2;
            size_t o0 = ((size_t)(b*DIM + row0))     * HW + col;
            size_t o1 = ((size_t)(b*DIM + row0 + 8)) * HW + col;
            *(float2*)&y[o0] = make_float2(acc[mt][nt][0], acc[mt][nt][1]);
            *(float2*)&y[o1] = make_float2(acc[mt][nt][2], acc[mt][nt][3]);
        }
    }
}

// ---------------- launch ----------------------------------------------------
extern "C" void kernel_launch(void* const* d_in, const int* in_sizes, int n_in,
                              void* d_out, int out_size)
{
    const float* k_fea = (const float*)d_in[0];
    const float* v_fea = (const float*)d_in[1];
    const float* q_fea = (const float*)d_in[2];
    const float* wq    = (const float*)d_in[3];
    const float* wk    = (const float*)d_in[4];
    const float* wv    = (const float*)d_in[5];
    const float* wproj = (const float*)d_in[6];
    const float* temp  = (const float*)d_in[7];
    const float* attw  = (const float*)d_in[8];
    float* y = (float*)d_out;

    static int smem_set = 0;
    if (!smem_set) {
        cudaFuncSetAttribute(finalgemm, cudaFuncAttributeMaxDynamicSharedMemorySize,
                             FG_SMEM);
        smem_set = 1;
    }

    zero_k<<<(B*HEADS*C*C + 255)/256, 256>>>();

    dim3 gconv(IMG/8, B*DIM);
    dwconv_k<<<gconv, 256>>>(q_fea, wq, 0);
    dwconv_k<<<gconv, 256>>>(k_fea, wk, 1);
    dwconv_k<<<gconv, 256>>>(v_fea, wv, 2);

    gemm_qk<<<dim3(QK_SPLITS, B*HEADS), 64>>>();

    rowcomb<<<(B*HEADS*C)/8, 256>>>(temp, attw);

    buildM<<<(B*DIM*DIM + 255)/256, 256>>>(wproj);

    finalgemm<<<dim3(HW/128, DIM/128, B), 256, FG_SMEM>>>(y);
}

// round 5
// speedup vs baseline: 6.1075x; 1.0780x over previous
#include <cuda_runtime.h>
#include <cuda_bf16.h>
#include <cstdint>
#include <math.h>

#define B 2
#define DIM 384
#define HEADS 8
#define C 48
#define IMG 128
#define HW (IMG*IMG)        // 16384
#define QK_SPLITS 64
#define QK_CHUNK (HW/QK_SPLITS)   // 256

// ---------------- scratch (static device globals; no allocations) ----------
__device__ __align__(16) float g_qc[B*DIM*HW];
__device__ __align__(16) float g_kc[B*DIM*HW];
__device__ __align__(16) __nv_bfloat16 g_vhi[B*DIM*HW];   // dwconv(v) hi, [b][ch][p]
__device__ __align__(16) __nv_bfloat16 g_vlo[B*DIM*HW];   // dwconv(v) lo
__device__ float g_ssq[B*DIM];
__device__ float g_ssk[B*DIM];
__device__ float g_G[B*HEADS*C*C];
__device__ float g_A[B*HEADS*C*C];
__device__ __align__(16) __nv_bfloat16 g_Mhi[B*DIM*DIM];  // [b][co][k] hi
__device__ __align__(16) __nv_bfloat16 g_Mlo[B*DIM*DIM];  // [b][co][k] lo

// ================= PTX helpers (compute_103-safe: sm_80+ features) =========
__device__ __forceinline__ uint32_t smem_u32(const void* p) {
    uint32_t a;
    asm("{ .reg .u64 t; cvta.to.shared.u64 t, %1; cvt.u32.u64 %0, t; }"
        : "=r"(a) : "l"(p));
    return a;
}
__device__ __forceinline__ void cpa16(uint32_t saddr, const void* g) {
    asm volatile("cp.async.cg.shared.global [%0], [%1], 16;"
                 :: "r"(saddr), "l"(g) : "memory");
}
#define CP_COMMIT() asm volatile("cp.async.commit_group;" ::: "memory")
#define CP_WAIT1()  asm volatile("cp.async.wait_group 1;" ::: "memory")

__device__ __forceinline__ void ldmA(uint32_t* a, uint32_t addr) {
    asm volatile("ldmatrix.sync.aligned.m8n8.x4.shared.b16 {%0,%1,%2,%3}, [%4];"
        : "=r"(a[0]), "=r"(a[1]), "=r"(a[2]), "=r"(a[3]) : "r"(addr));
}
// x4 transposed B load: returns fragments for TWO adjacent n8 tiles.
__device__ __forceinline__ void ldmBt4(uint32_t* bf, uint32_t addr) {
    asm volatile("ldmatrix.sync.aligned.m8n8.x4.trans.shared.b16 {%0,%1,%2,%3}, [%4];"
        : "=r"(bf[0]), "=r"(bf[1]), "=r"(bf[2]), "=r"(bf[3]) : "r"(addr));
}
__device__ __forceinline__ void mma16816(float* c, const uint32_t* a, const uint32_t* bf) {
    asm volatile("mma.sync.aligned.m16n8k16.row.col.f32.bf16.bf16.f32 "
        "{%0,%1,%2,%3}, {%4,%5,%6,%7}, {%8,%9}, {%0,%1,%2,%3};"
        : "+f"(c[0]), "+f"(c[1]), "+f"(c[2]), "+f"(c[3])
        : "r"(a[0]), "r"(a[1]), "r"(a[2]), "r"(a[3]), "r"(bf[0]), "r"(bf[1]));
}

// ---------------- zero accumulators ----------------------------------------
__global__ void zero_k() {
    int i = blockIdx.x * blockDim.x + threadIdx.x;
    if (i < B*DIM) { g_ssq[i] = 0.f; g_ssk[i] = 0.f; }
    if (i < B*HEADS*C*C) g_G[i] = 0.f;
}

// ---------------- fused depthwise 3x3 convs, sliding-window rows -----------
// blockIdx.z selects tensor (0=q, 1=k, 2=v). One block per (b,channel) image.
// Each warp owns 16 consecutive rows; every input row loaded exactly once
// by the warps that need it (register rotation), halos via shuffle.
__device__ __forceinline__ uint32_t pack_bf2(float a, float b) {
    __nv_bfloat162 t(__float2bfloat16(a), __float2bfloat16(b));
    return *reinterpret_cast<uint32_t*>(&t);
}
__global__ void __launch_bounds__(256) dwconv_all(
    const float* __restrict__ qf, const float* __restrict__ kf,
    const float* __restrict__ vf, const float* __restrict__ wq,
    const float* __restrict__ wk, const float* __restrict__ wv)
{
    int which = blockIdx.z;
    const float* in = (which == 0) ? qf : (which == 1) ? kf : vf;
    const float* w  = (which == 0) ? wq : (which == 1) ? wk : wv;
    int bc  = blockIdx.y;
    int c   = bc % DIM;
    int wid = threadIdx.x >> 5, lid = threadIdx.x & 31;
    int y0  = wid * 16;
    int x   = lid * 4;
    const float* ip = in + (size_t)bc * HW;

    float wv9[9];
#pragma unroll
    for (int i = 0; i < 9; i++) wv9[i] = w[c*9 + i];

    float4 mP, mC, mN;
    float lP, rP, lC, rC, lN, rN;

    auto loadrow = [&](int yy, float4& m, float& l, float& r) {
        if ((unsigned)yy < (unsigned)IMG) m = *(const float4*)(ip + yy*IMG + x);
        else m = make_float4(0.f, 0.f, 0.f, 0.f);
        l = __shfl_up_sync(0xffffffffu, m.w, 1);
        r = __shfl_down_sync(0xffffffffu, m.x, 1);
        if (lid == 0)  l = 0.f;
        if (lid == 31) r = 0.f;
    };

    loadrow(y0 - 1, mP, lP, rP);
    loadrow(y0,     mC, lC, rC);

    float ssum = 0.f;
#pragma unroll 4
    for (int yy = 0; yy < 16; yy++) {
        loadrow(y0 + yy + 1, mN, lN, rN);

        float a0 = wv9[0]*lP   + wv9[1]*mP.x + wv9[2]*mP.y
                 + wv9[3]*lC   + wv9[4]*mC.x + wv9[5]*mC.y
                 + wv9[6]*lN   + wv9[7]*mN.x + wv9[8]*mN.y;
        float a1 = wv9[0]*mP.x + wv9[1]*mP.y + wv9[2]*mP.z
                 + wv9[3]*mC.x + wv9[4]*mC.y + wv9[5]*mC.z
                 + wv9[6]*mN.x + wv9[7]*mN.y + wv9[8]*mN.z;
        float a2 = wv9[0]*mP.y + wv9[1]*mP.z + wv9[2]*mP.w
                 + wv9[3]*mC.y + wv9[4]*mC.z + wv9[5]*mC.w
                 + wv9[6]*mN.y + wv9[7]*mN.z + wv9[8]*mN.w;
        float a3 = wv9[0]*mP.z + wv9[1]*mP.w + wv9[2]*rP
                 + wv9[3]*mC.z + wv9[4]*mC.w + wv9[5]*rC
                 + wv9[6]*mN.z + wv9[7]*mN.w + wv9[8]*rN;

        size_t po = (size_t)bc*HW + (y0 + yy)*IMG + x;
        if (which == 2) {
            float h0 = __bfloat162float(__float2bfloat16(a0));
            float h1 = __bfloat162float(__float2bfloat16(a1));
            float h2 = __bfloat162float(__float2bfloat16(a2));
            float h3 = __bfloat162float(__float2bfloat16(a3));
            uint2 uh, ul;
            uh.x = pack_bf2(a0, a1); uh.y = pack_bf2(a2, a3);
            ul.x = pack_bf2(a0 - h0, a1 - h1); ul.y = pack_bf2(a2 - h2, a3 - h3);
            *(uint2*)&g_vhi[po] = uh;
            *(uint2*)&g_vlo[po] = ul;
        } else {
            float* out = (which == 0) ? g_qc : g_kc;
            *(float4*)&out[po] = make_float4(a0, a1, a2, a3);
            ssum += a0*a0 + a1*a1 + a2*a2 + a3*a3;
        }
        mP = mC; lP = lC; rP = rC;
        mC = mN; lC = lN; rC = rN;
    }

    if (which < 2) {
#pragma unroll
        for (int off = 16; off > 0; off >>= 1)
            ssum += __shfl_xor_sync(0xffffffffu, ssum, off);
        if (lid == 0) {
            float* ssq = (which == 0) ? g_ssq : g_ssk;
            atomicAdd(&ssq[bc], ssum);
        }
    }
}

// ---------------- G = Q @ K^T, 64 threads, 6x6 per thread ------------------
__global__ void __launch_bounds__(64) gemm_qk()
{
    __shared__ float Qs[C][33];
    __shared__ float Ks[C][33];
    int bh = blockIdx.y;
    int b  = bh >> 3, hd = bh & 7;
    size_t base = ((size_t)(b*DIM + hd*C)) * HW + (size_t)blockIdx.x * QK_CHUNK;

    int tid = threadIdx.x;
    int ty = tid >> 3, tx = tid & 7;

    float acc[6][6];
#pragma unroll
    for (int i = 0; i < 6; i++)
#pragma unroll
        for (int j = 0; j < 6; j++) acc[i][j] = 0.f;

    for (int kt = 0; kt < QK_CHUNK; kt += 32) {
        for (int i = tid; i < C*32; i += 64) {
            int r = i >> 5, kk = i & 31;
            size_t off = base + (size_t)r * HW + kt + kk;
            Qs[r][kk] = g_qc[off];
            Ks[r][kk] = g_kc[off];
        }
        __syncthreads();
#pragma unroll 4
        for (int kk = 0; kk < 32; kk++) {
            float qv[6], kv[6];
#pragma unroll
            for (int i = 0; i < 6; i++) { qv[i] = Qs[ty*6 + i][kk]; kv[i] = Ks[tx*6 + i][kk]; }
#pragma unroll
            for (int i = 0; i < 6; i++)
#pragma unroll
                for (int j = 0; j < 6; j++) acc[i][j] += qv[i] * kv[j];
        }
        __syncthreads();
    }
    float* Gb = &g_G[bh * C * C];
#pragma unroll
    for (int i = 0; i < 6; i++)
#pragma unroll
        for (int j = 0; j < 6; j++)
            atomicAdd(&Gb[(ty*6 + i)*C + (tx*6 + j)], acc[i][j]);
}

// ---------------- rowcomb: warp-per-row, rank-based ------------------------
__global__ void __launch_bounds__(256) rowcomb(const float* __restrict__ temp,
                                               const float* __restrict__ attw)
{
    __shared__ float sv[8][48];
    int wid = threadIdx.x >> 5, lid = threadIdx.x & 31;
    int row = blockIdx.x * 8 + wid;
    int b   = row / (HEADS*C);
    int rem = row % (HEADS*C);
    int hd  = rem / C, c = rem % C;

    float inq = 1.f / fmaxf(sqrtf(g_ssq[b*DIM + hd*C + c]), 1e-12f);
    float t   = temp[hd];
    const float* Gr = &g_G[((b*HEADS + hd)*C + c) * C];

    float v0, v1 = -1e30f;
    {
        float ink = 1.f / fmaxf(sqrtf(g_ssk[b*DIM + hd*C + lid]), 1e-12f);
        v0 = Gr[lid] * inq * ink * t;
        sv[wid][lid] = v0;
        if (lid < 16) {
            int d = lid + 32;
            float ink2 = 1.f / fmaxf(sqrtf(g_ssk[b*DIM + hd*C + d]), 1e-12f);
            v1 = Gr[d] * inq * ink2 * t;
            sv[wid][d] = v1;
        }
    }
    __syncwarp();

    float m = fmaxf(v0, v1);
#pragma unroll
    for (int off = 16; off > 0; off >>= 1)
        m = fmaxf(m, __shfl_xor_sync(0xffffffffu, m, off));

    int r0 = 0, r1 = 0;
#pragma unroll 8
    for (int j = 0; j < C; j++) {
        float vj = sv[wid][j];
        r0 += (vj > v0) || (vj == v0 && j < lid);
        if (lid < 16) r1 += (vj > v1) || (vj == v1 && j < lid + 32);
    }
    float e0 = expf(v0 - m);
    float e1 = (lid < 16) ? expf(v1 - m) : 0.f;

    const int kl[4] = {C/2, C*2/3, C*3/4, C*4/5};
    float ds[4];
#pragma unroll
    for (int i = 0; i < 4; i++)
        ds[i] = ((r0 < kl[i]) ? e0 : 0.f) + ((lid < 16 && r1 < kl[i]) ? e1 : 0.f);
#pragma unroll
    for (int off = 16; off > 0; off >>= 1) {
#pragma unroll
        for (int i = 0; i < 4; i++)
            ds[i] += __shfl_xor_sync(0xffffffffu, ds[i], off);
    }

    float cf0 = 0.f, cf1 = 0.f;
#pragma unroll
    for (int i = 0; i < 4; i++) {
        float wdi = attw[i] / ds[i];
        if (r0 < kl[i]) cf0 += wdi;
        if (r1 < kl[i]) cf1 += wdi;
    }

    float* Ar = &g_A[((b*HEADS + hd)*C + c) * C];
    Ar[lid] = e0 * cf0;
    if (lid < 16) Ar[lid + 32] = e1 * cf1;
}

// ---------------- M[b] = Wproj @ blockdiag(A[b]), split to bf16 hi/lo ------
__global__ void buildM(const float* __restrict__ wproj)
{
    int idx = blockIdx.x * blockDim.x + threadIdx.x;
    if (idx >= B*DIM*DIM) return;
    int b  = idx / (DIM*DIM);
    int r  = idx % (DIM*DIM);
    int co = r / DIM;
    int g  = r % DIM;
    int hh = g / C, dl = g % C;

    const float* wp = wproj + co*DIM + hh*C;
    const float* Ac = &g_A[((b*HEADS + hh)*C) * C + dl];
    float acc = 0.f;
#pragma unroll
    for (int cc = 0; cc < C; cc++) acc += wp[cc] * Ac[cc*C];
    __nv_bfloat16 hi = __float2bfloat16(acc);
    g_Mhi[idx] = hi;
    g_Mlo[idx] = __float2bfloat16(acc - __bfloat162float(hi));
}

// ---------------- final GEMM via ldmatrix + mma.sync bf16 split-precision --
#define AST_B 80
#define BST_B 272
#define A_STG (128*AST_B)
#define B_STG (32*BST_B)
#define OFF_AHI 0
#define OFF_ALO (2*A_STG)
#define OFF_BHI (4*A_STG)
#define OFF_BLO (4*A_STG + 2*B_STG)
#define FG_SMEM (4*A_STG + 4*B_STG)
#define NKC 12

__global__ void __launch_bounds__(256, 2) finalgemm(float* __restrict__ y)
{
    extern __shared__ char smem[];
    uint32_t sb = smem_u32(smem);
    int tid = threadIdx.x, wid = tid >> 5, lid = tid & 31;
    int b   = blockIdx.z;
    int co0 = blockIdx.y * 128;
    int p0  = blockIdx.x * 128;
    int wm  = (wid & 1) * 64;
    int wn  = (wid >> 1) * 32;

    const __nv_bfloat16* Mh = g_Mhi + (size_t)b * DIM * DIM;
    const __nv_bfloat16* Ml = g_Mlo + (size_t)b * DIM * DIM;
    const __nv_bfloat16* Vh = g_vhi + (size_t)b * DIM * HW;
    const __nv_bfloat16* Vl = g_vlo + (size_t)b * DIM * HW;

    float acc[4][4][4];
#pragma unroll
    for (int mt = 0; mt < 4; mt++)
#pragma unroll
        for (int nt = 0; nt < 4; nt++)
#pragma unroll
            for (int i = 0; i < 4; i++) acc[mt][nt][i] = 0.f;

    auto load_chunk = [&](int kc, int st) {
        int k0 = kc * 32;
#pragma unroll
        for (int i = tid; i < 512; i += 256) {
            int r = i >> 2, cc = i & 3;
            size_t go = (size_t)(co0 + r)*DIM + k0 + cc*8;
            uint32_t so = r*AST_B + cc*16;
            cpa16(sb + OFF_AHI + st*A_STG + so, Mh + go);
            cpa16(sb + OFF_ALO + st*A_STG + so, Ml + go);
        }
#pragma unroll
        for (int i = tid; i < 512; i += 256) {
            int r = i >> 4, cc = i & 15;
            size_t go = (size_t)(k0 + r)*HW + p0 + cc*8;
            uint32_t so = r*BST_B + cc*16;
            cpa16(sb + OFF_BHI + st*B_STG + so, Vh + go);
            cpa16(sb + OFF_BLO + st*B_STG + so, Vl + go);
        }
    };

    load_chunk(0, 0);
    CP_COMMIT();

    for (int kc = 0; kc < NKC; kc++) {
        int st = kc & 1;
        if (kc + 1 < NKC) load_chunk(kc + 1, (kc + 1) & 1);
        CP_COMMIT();
        CP_WAIT1();
        __syncthreads();

        uint32_t aAh = sb + OFF_AHI + st*A_STG + (wm + (lid & 15))*AST_B + (lid >> 4)*16;
        uint32_t aAl = aAh + (OFF_ALO - OFF_AHI);
        // x4 trans B: lanes 0-15 -> k rows of first n8 pair col, lanes 16-31 second
        uint32_t aBh = sb + OFF_BHI + st*B_STG + (lid & 15)*BST_B + wn*2 + (lid >> 4)*16;
        uint32_t aBl = aBh + (OFF_BLO - OFF_BHI);

#pragma unroll
        for (int ks = 0; ks < 2; ks++) {
            uint32_t Ah[4][4], Al[4][4];
#pragma unroll
            for (int mt = 0; mt < 4; mt++) {
                ldmA(Ah[mt], aAh + mt*16*AST_B + ks*32);
                ldmA(Al[mt], aAl + mt*16*AST_B + ks*32);
            }
#pragma unroll
            for (int nt0 = 0; nt0 < 4; nt0 += 2) {
                uint32_t Bh[4], Bl[4];
                ldmBt4(Bh, aBh + ks*16*BST_B + nt0*16);
                ldmBt4(Bl, aBl + ks*16*BST_B + nt0*16);
#pragma unroll
                for (int q = 0; q < 2; q++) {
#pragma unroll
                    for (int mt = 0; mt < 4; mt++) {
                        mma16816(acc[mt][nt0+q], Ah[mt], &Bh[q*2]);
                        mma16816(acc[mt][nt0+q], Ah[mt], &Bl[q*2]);
                        mma16816(acc[mt][nt0+q], Al[mt], &Bh[q*2]);
                    }
                }
            }
        }
        __syncthreads();
    }

    int group = lid >> 2, tg = lid & 3;
#pragma unroll
    for (int mt = 0; mt < 4; mt++) {
        int row0 = co0 + wm + mt*16 + group;
#pragma unroll
        for (int nt = 0; nt < 4; nt++) {
            int col = p0 + wn + nt*8 + tg*2;
            size_t o0 = ((size_t)(b*DIM + row0))     * HW + col;
            size_t o1 = ((size_t)(b*DIM + row0 + 8)) * HW + col;
            *(float2*)&y[o0] = make_float2(acc[mt][nt][0], acc[mt][nt][1]);
            *(float2*)&y[o1] = make_float2(acc[mt][nt][2], acc[mt][nt][3]);
        }
    }
}

// ---------------- launch ----------------------------------------------------
extern "C" void kernel_launch(void* const* d_in, const int* in_sizes, int n_in,
                              void* d_out, int out_size)
{
    const float* k_fea = (const float*)d_in[0];
    const float* v_fea = (const float*)d_in[1];
    const float* q_fea = (const float*)d_in[2];
    const float* wq    = (const float*)d_in[3];
    const float* wk    = (const float*)d_in[4];
    const float* wv    = (const float*)d_in[5];
    const float* wproj = (const float*)d_in[6];
    const float* temp  = (const float*)d_in[7];
    const float* attw  = (const float*)d_in[8];
    float* y = (float*)d_out;

    static int smem_set = 0;
    if (!smem_set) {
        cudaFuncSetAttribute(finalgemm, cudaFuncAttributeMaxDynamicSharedMemorySize,
                             FG_SMEM);
        smem_set = 1;
    }

    zero_k<<<(B*HEADS*C*C + 255)/256, 256>>>();

    dwconv_all<<<dim3(1, B*DIM, 3), 256>>>(q_fea, k_fea, v_fea, wq, wk, wv);

    gemm_qk<<<dim3(QK_SPLITS, B*HEADS), 64>>>();

    rowcomb<<<(B*HEADS*C)/8, 256>>>(temp, attw);

    buildM<<<(B*DIM*DIM + 255)/256, 256>>>(wproj);

    finalgemm<<<dim3(HW/128, DIM/128, B), 256, FG_SMEM>>>(y);
}

// round 6
// speedup vs baseline: 6.7715x; 1.1087x over previous
#include <cuda_runtime.h>
#include <cuda_fp16.h>
#include <cstdint>
#include <math.h>

#define B 2
#define DIM 384
#define HEADS 8
#define C 48
#define IMG 128
#define HW (IMG*IMG)        // 16384
#define QK_SPLITS 64
#define QK_CHUNK (HW/QK_SPLITS)   // 256

// ---------------- scratch (static device globals; no allocations) ----------
__device__ __align__(16) float g_qc[B*DIM*HW];
__device__ __align__(16) float g_kc[B*DIM*HW];
__device__ __align__(16) __half g_vh[B*DIM*HW];           // dwconv(v) fp16, [b][ch][p]
__device__ float g_ssq[B*DIM];
__device__ float g_ssk[B*DIM];
__device__ float g_G[B*HEADS*C*C];
__device__ float g_A[B*HEADS*C*C];
__device__ __align__(16) __half g_Mhi[B*DIM*DIM];         // [b][co][k] fp16 hi
__device__ __align__(16) __half g_Mlo[B*DIM*DIM];         // [b][co][k] fp16 lo

// ================= PTX helpers (compute_103-safe: sm_80+ features) =========
__device__ __forceinline__ uint32_t smem_u32(const void* p) {
    uint32_t a;
    asm("{ .reg .u64 t; cvta.to.shared.u64 t, %1; cvt.u32.u64 %0, t; }"
        : "=r"(a) : "l"(p));
    return a;
}
__device__ __forceinline__ void cpa16(uint32_t saddr, const void* g) {
    asm volatile("cp.async.cg.shared.global [%0], [%1], 16;"
                 :: "r"(saddr), "l"(g) : "memory");
}
#define CP_COMMIT() asm volatile("cp.async.commit_group;" ::: "memory")
#define CP_WAIT1()  asm volatile("cp.async.wait_group 1;" ::: "memory")

__device__ __forceinline__ void ldmA(uint32_t* a, uint32_t addr) {
    asm volatile("ldmatrix.sync.aligned.m8n8.x4.shared.b16 {%0,%1,%2,%3}, [%4];"
        : "=r"(a[0]), "=r"(a[1]), "=r"(a[2]), "=r"(a[3]) : "r"(addr));
}
// x4 transposed B load: fragments for TWO adjacent n8 tiles.
__device__ __forceinline__ void ldmBt4(uint32_t* bf, uint32_t addr) {
    asm volatile("ldmatrix.sync.aligned.m8n8.x4.trans.shared.b16 {%0,%1,%2,%3}, [%4];"
        : "=r"(bf[0]), "=r"(bf[1]), "=r"(bf[2]), "=r"(bf[3]) : "r"(addr));
}
__device__ __forceinline__ void mma16816(float* c, const uint32_t* a, const uint32_t* bf) {
    asm volatile("mma.sync.aligned.m16n8k16.row.col.f32.f16.f16.f32 "
        "{%0,%1,%2,%3}, {%4,%5,%6,%7}, {%8,%9}, {%0,%1,%2,%3};"
        : "+f"(c[0]), "+f"(c[1]), "+f"(c[2]), "+f"(c[3])
        : "r"(a[0]), "r"(a[1]), "r"(a[2]), "r"(a[3]), "r"(bf[0]), "r"(bf[1]));
}

// ---------------- zero accumulators ----------------------------------------
__global__ void zero_k() {
    int i = blockIdx.x * blockDim.x + threadIdx.x;
    if (i < B*DIM) { g_ssq[i] = 0.f; g_ssk[i] = 0.f; }
    if (i < B*HEADS*C*C) g_G[i] = 0.f;
}

// ---------------- fused depthwise 3x3 convs, sliding-window rows -----------
__device__ __forceinline__ uint32_t pack_h2(float a, float b) {
    __half2 t(__float2half(a), __float2half(b));
    return *reinterpret_cast<uint32_t*>(&t);
}
__global__ void __launch_bounds__(256) dwconv_all(
    const float* __restrict__ qf, const float* __restrict__ kf,
    const float* __restrict__ vf, const float* __restrict__ wq,
    const float* __restrict__ wk, const float* __restrict__ wv)
{
    int which = blockIdx.z;
    const float* in = (which == 0) ? qf : (which == 1) ? kf : vf;
    const float* w  = (which == 0) ? wq : (which == 1) ? wk : wv;
    int bc  = blockIdx.y;
    int c   = bc % DIM;
    int wid = threadIdx.x >> 5, lid = threadIdx.x & 31;
    int y0  = wid * 16;
    int x   = lid * 4;
    const float* ip = in + (size_t)bc * HW;

    float wv9[9];
#pragma unroll
    for (int i = 0; i < 9; i++) wv9[i] = w[c*9 + i];

    float4 mP, mC, mN;
    float lP, rP, lC, rC, lN, rN;

    auto loadrow = [&](int yy, float4& m, float& l, float& r) {
        if ((unsigned)yy < (unsigned)IMG) m = *(const float4*)(ip + yy*IMG + x);
        else m = make_float4(0.f, 0.f, 0.f, 0.f);
        l = __shfl_up_sync(0xffffffffu, m.w, 1);
        r = __shfl_down_sync(0xffffffffu, m.x, 1);
        if (lid == 0)  l = 0.f;
        if (lid == 31) r = 0.f;
    };

    loadrow(y0 - 1, mP, lP, rP);
    loadrow(y0,     mC, lC, rC);

    float ssum = 0.f;
#pragma unroll 4
    for (int yy = 0; yy < 16; yy++) {
        loadrow(y0 + yy + 1, mN, lN, rN);

        float a0 = wv9[0]*lP   + wv9[1]*mP.x + wv9[2]*mP.y
                 + wv9[3]*lC   + wv9[4]*mC.x + wv9[5]*mC.y
                 + wv9[6]*lN   + wv9[7]*mN.x + wv9[8]*mN.y;
        float a1 = wv9[0]*mP.x + wv9[1]*mP.y + wv9[2]*mP.z
                 + wv9[3]*mC.x + wv9[4]*mC.y + wv9[5]*mC.z
                 + wv9[6]*mN.x + wv9[7]*mN.y + wv9[8]*mN.z;
        float a2 = wv9[0]*mP.y + wv9[1]*mP.z + wv9[2]*mP.w
                 + wv9[3]*mC.y + wv9[4]*mC.z + wv9[5]*mC.w
                 + wv9[6]*mN.y + wv9[7]*mN.z + wv9[8]*mN.w;
        float a3 = wv9[0]*mP.z + wv9[1]*mP.w + wv9[2]*rP
                 + wv9[3]*mC.z + wv9[4]*mC.w + wv9[5]*rC
                 + wv9[6]*mN.z + wv9[7]*mN.w + wv9[8]*rN;

        size_t po = (size_t)bc*HW + (y0 + yy)*IMG + x;
        if (which == 2) {
            uint2 uh;
            uh.x = pack_h2(a0, a1); uh.y = pack_h2(a2, a3);
            *(uint2*)&g_vh[po] = uh;
        } else {
            float* out = (which == 0) ? g_qc : g_kc;
            *(float4*)&out[po] = make_float4(a0, a1, a2, a3);
            ssum += a0*a0 + a1*a1 + a2*a2 + a3*a3;
        }
        mP = mC; lP = lC; rP = rC;
        mC = mN; lC = lN; rC = rN;
    }

    if (which < 2) {
#pragma unroll
        for (int off = 16; off > 0; off >>= 1)
            ssum += __shfl_xor_sync(0xffffffffu, ssum, off);
        if (lid == 0) {
            float* ssq = (which == 0) ? g_ssq : g_ssk;
            atomicAdd(&ssq[bc], ssum);
        }
    }
}

// ---------------- G = Q @ K^T, 64 threads, 6x6 per thread ------------------
__global__ void __launch_bounds__(64) gemm_qk()
{
    __shared__ float Qs[C][33];
    __shared__ float Ks[C][33];
    int bh = blockIdx.y;
    int b  = bh >> 3, hd = bh & 7;
    size_t base = ((size_t)(b*DIM + hd*C)) * HW + (size_t)blockIdx.x * QK_CHUNK;

    int tid = threadIdx.x;
    int ty = tid >> 3, tx = tid & 7;

    float acc[6][6];
#pragma unroll
    for (int i = 0; i < 6; i++)
#pragma unroll
        for (int j = 0; j < 6; j++) acc[i][j] = 0.f;

    for (int kt = 0; kt < QK_CHUNK; kt += 32) {
        for (int i = tid; i < C*32; i += 64) {
            int r = i >> 5, kk = i & 31;
            size_t off = base + (size_t)r * HW + kt + kk;
            Qs[r][kk] = g_qc[off];
            Ks[r][kk] = g_kc[off];
        }
        __syncthreads();
#pragma unroll 4
        for (int kk = 0; kk < 32; kk++) {
            float qv[6], kv[6];
#pragma unroll
            for (int i = 0; i < 6; i++) { qv[i] = Qs[ty*6 + i][kk]; kv[i] = Ks[tx*6 + i][kk]; }
#pragma unroll
            for (int i = 0; i < 6; i++)
#pragma unroll
                for (int j = 0; j < 6; j++) acc[i][j] += qv[i] * kv[j];
        }
        __syncthreads();
    }
    float* Gb = &g_G[bh * C * C];
#pragma unroll
    for (int i = 0; i < 6; i++)
#pragma unroll
        for (int j = 0; j < 6; j++)
            atomicAdd(&Gb[(ty*6 + i)*C + (tx*6 + j)], acc[i][j]);
}

// ---------------- rowcomb: warp-per-row, rank-based ------------------------
__global__ void __launch_bounds__(256) rowcomb(const float* __restrict__ temp,
                                               const float* __restrict__ attw)
{
    __shared__ float sv[8][48];
    int wid = threadIdx.x >> 5, lid = threadIdx.x & 31;
    int row = blockIdx.x * 8 + wid;
    int b   = row / (HEADS*C);
    int rem = row % (HEADS*C);
    int hd  = rem / C, c = rem % C;

    float inq = 1.f / fmaxf(sqrtf(g_ssq[b*DIM + hd*C + c]), 1e-12f);
    float t   = temp[hd];
    const float* Gr = &g_G[((b*HEADS + hd)*C + c) * C];

    float v0, v1 = -1e30f;
    {
        float ink = 1.f / fmaxf(sqrtf(g_ssk[b*DIM + hd*C + lid]), 1e-12f);
        v0 = Gr[lid] * inq * ink * t;
        sv[wid][lid] = v0;
        if (lid < 16) {
            int d = lid + 32;
            float ink2 = 1.f / fmaxf(sqrtf(g_ssk[b*DIM + hd*C + d]), 1e-12f);
            v1 = Gr[d] * inq * ink2 * t;
            sv[wid][d] = v1;
        }
    }
    __syncwarp();

    float m = fmaxf(v0, v1);
#pragma unroll
    for (int off = 16; off > 0; off >>= 1)
        m = fmaxf(m, __shfl_xor_sync(0xffffffffu, m, off));

    int r0 = 0, r1 = 0;
#pragma unroll 8
    for (int j = 0; j < C; j++) {
        float vj = sv[wid][j];
        r0 += (vj > v0) || (vj == v0 && j < lid);
        if (lid < 16) r1 += (vj > v1) || (vj == v1 && j < lid + 32);
    }
    float e0 = expf(v0 - m);
    float e1 = (lid < 16) ? expf(v1 - m) : 0.f;

    const int kl[4] = {C/2, C*2/3, C*3/4, C*4/5};
    float ds[4];
#pragma unroll
    for (int i = 0; i < 4; i++)
        ds[i] = ((r0 < kl[i]) ? e0 : 0.f) + ((lid < 16 && r1 < kl[i]) ? e1 : 0.f);
#pragma unroll
    for (int off = 16; off > 0; off >>= 1) {
#pragma unroll
        for (int i = 0; i < 4; i++)
            ds[i] += __shfl_xor_sync(0xffffffffu, ds[i], off);
    }

    float cf0 = 0.f, cf1 = 0.f;
#pragma unroll
    for (int i = 0; i < 4; i++) {
        float wdi = attw[i] / ds[i];
        if (r0 < kl[i]) cf0 += wdi;
        if (r1 < kl[i]) cf1 += wdi;
    }

    float* Ar = &g_A[((b*HEADS + hd)*C + c) * C];
    Ar[lid] = e0 * cf0;
    if (lid < 16) Ar[lid + 32] = e1 * cf1;
}

// ---------------- M[b] = Wproj @ blockdiag(A[b]), split to fp16 hi/lo ------
__global__ void buildM(const float* __restrict__ wproj)
{
    int idx = blockIdx.x * blockDim.x + threadIdx.x;
    if (idx >= B*DIM*DIM) return;
    int b  = idx / (DIM*DIM);
    int r  = idx % (DIM*DIM);
    int co = r / DIM;
    int g  = r % DIM;
    int hh = g / C, dl = g % C;

    const float* wp = wproj + co*DIM + hh*C;
    const float* Ac = &g_A[((b*HEADS + hh)*C) * C + dl];
    float acc = 0.f;
#pragma unroll
    for (int cc = 0; cc < C; cc++) acc += wp[cc] * Ac[cc*C];
    __half hi = __float2half(acc);
    g_Mhi[idx] = hi;
    g_Mlo[idx] = __float2half(acc - __half2float(hi));
}

// ---------------- final GEMM: fp16 2-term split (Mhi+Mlo) @ V_fp16 ---------
#define AST_B 80
#define BST_B 272
#define A_STG (128*AST_B)      // 10240
#define B_STG (32*BST_B)       // 8704
#define OFF_AHI 0
#define OFF_ALO (2*A_STG)      // 20480
#define OFF_BHI (4*A_STG)      // 40960
#define FG_SMEM (4*A_STG + 2*B_STG)   // 58368
#define NKC 12

__global__ void __launch_bounds__(256, 2) finalgemm(float* __restrict__ y)
{
    extern __shared__ char smem[];
    uint32_t sb = smem_u32(smem);
    int tid = threadIdx.x, wid = tid >> 5, lid = tid & 31;
    int b   = blockIdx.z;
    int co0 = blockIdx.y * 128;
    int p0  = blockIdx.x * 128;
    int wm  = (wid & 1) * 64;
    int wn  = (wid >> 1) * 32;

    const __half* Mh = g_Mhi + (size_t)b * DIM * DIM;
    const __half* Ml = g_Mlo + (size_t)b * DIM * DIM;
    const __half* Vh = g_vh  + (size_t)b * DIM * HW;

    float acc[4][4][4];
#pragma unroll
    for (int mt = 0; mt < 4; mt++)
#pragma unroll
        for (int nt = 0; nt < 4; nt++)
#pragma unroll
            for (int i = 0; i < 4; i++) acc[mt][nt][i] = 0.f;

    auto load_chunk = [&](int kc, int st) {
        int k0 = kc * 32;
#pragma unroll
        for (int i = tid; i < 512; i += 256) {
            int r = i >> 2, cc = i & 3;
            size_t go = (size_t)(co0 + r)*DIM + k0 + cc*8;
            uint32_t so = r*AST_B + cc*16;
            cpa16(sb + OFF_AHI + st*A_STG + so, Mh + go);
            cpa16(sb + OFF_ALO + st*A_STG + so, Ml + go);
        }
#pragma unroll
        for (int i = tid; i < 512; i += 256) {
            int r = i >> 4, cc = i & 15;
            size_t go = (size_t)(k0 + r)*HW + p0 + cc*8;
            uint32_t so = r*BST_B + cc*16;
            cpa16(sb + OFF_BHI + st*B_STG + so, Vh + go);
        }
    };

    load_chunk(0, 0);
    CP_COMMIT();

    for (int kc = 0; kc < NKC; kc++) {
        int st = kc & 1;
        if (kc + 1 < NKC) load_chunk(kc + 1, (kc + 1) & 1);
        CP_COMMIT();
        CP_WAIT1();
        __syncthreads();

        uint32_t aAh = sb + OFF_AHI + st*A_STG + (wm + (lid & 15))*AST_B + (lid >> 4)*16;
        uint32_t aAl = aAh + (OFF_ALO - OFF_AHI);
        uint32_t aBh = sb + OFF_BHI + st*B_STG + (lid & 15)*BST_B + wn*2 + (lid >> 4)*16;

#pragma unroll
        for (int ks = 0; ks < 2; ks++) {
            uint32_t Ah[4][4], Al[4][4];
#pragma unroll
            for (int mt = 0; mt < 4; mt++) {
                ldmA(Ah[mt], aAh + mt*16*AST_B + ks*32);
                ldmA(Al[mt], aAl + mt*16*AST_B + ks*32);
            }
#pragma unroll
            for (int nt0 = 0; nt0 < 4; nt0 += 2) {
                uint32_t Bh[4];
                ldmBt4(Bh, aBh + ks*16*BST_B + nt0*16);
#pragma unroll
                for (int q = 0; q < 2; q++) {
#pragma unroll
                    for (int mt = 0; mt < 4; mt++) {
                        mma16816(acc[mt][nt0+q], Ah[mt], &Bh[q*2]);
                        mma16816(acc[mt][nt0+q], Al[mt], &Bh[q*2]);
                    }
                }
            }
        }
        __syncthreads();
    }

    int group = lid >> 2, tg = lid & 3;
#pragma unroll
    for (int mt = 0; mt < 4; mt++) {
        int row0 = co0 + wm + mt*16 + group;
#pragma unroll
        for (int nt = 0; nt < 4; nt++) {
            int col = p0 + wn + nt*8 + tg*2;
            size_t o0 = ((size_t)(b*DIM + row0))     * HW + col;
            size_t o1 = ((size_t)(b*DIM + row0 + 8)) * HW + col;
            *(float2*)&y[o0] = make_float2(acc[mt][nt][0], acc[mt][nt][1]);
            *(float2*)&y[o1] = make_float2(acc[mt][nt][2], acc[mt][nt][3]);
        }
    }
}

// ---------------- launch ----------------------------------------------------
extern "C" void kernel_launch(void* const* d_in, const int* in_sizes, int n_in,
                              void* d_out, int out_size)
{
    const float* k_fea = (const float*)d_in[0];
    const float* v_fea = (const float*)d_in[1];
    const float* q_fea = (const float*)d_in[2];
    const float* wq    = (const float*)d_in[3];
    const float* wk    = (const float*)d_in[4];
    const float* wv    = (const float*)d_in[5];
    const float* wproj = (const float*)d_in[6];
    const float* temp  = (const float*)d_in[7];
    const float* attw  = (const float*)d_in[8];
    float* y = (float*)d_out;

    static int smem_set = 0;
    if (!smem_set) {
        cudaFuncSetAttribute(finalgemm, cudaFuncAttributeMaxDynamicSharedMemorySize,
                             FG_SMEM);
        smem_set = 1;
    }

    zero_k<<<(B*HEADS*C*C + 255)/256, 256>>>();

    dwconv_all<<<dim3(1, B*DIM, 3), 256>>>(q_fea, k_fea, v_fea, wq, wk, wv);

    gemm_qk<<<dim3(QK_SPLITS, B*HEADS), 64>>>();

    rowcomb<<<(B*HEADS*C)/8, 256>>>(temp, attw);

    buildM<<<(B*DIM*DIM + 255)/256, 256>>>(wproj);

    finalgemm<<<dim3(HW/128, DIM/128, B), 256, FG_SMEM>>>(y);
}

// round 7
// speedup vs baseline: 8.4490x; 1.2477x over previous
#include <cuda_runtime.h>
#include <cuda_fp16.h>
#include <cstdint>
#include <math.h>

#define B 2
#define DIM 384
#define HEADS 8
#define C 48
#define IMG 128
#define HW (IMG*IMG)        // 16384
#define QK_SPLITS 32

// ---------------- scratch (static device globals; no allocations) ----------
__device__ __align__(16) __half g_qh[B*DIM*HW];   // dwconv(q) fp16 hi
__device__ __align__(16) __half g_ql[B*DIM*HW];   // dwconv(q) fp16 lo
__device__ __align__(16) __half g_kh[B*DIM*HW];   // dwconv(k) fp16 hi
__device__ __align__(16) __half g_kl[B*DIM*HW];   // dwconv(k) fp16 lo
__device__ __align__(16) __half g_vh[B*DIM*HW];   // dwconv(v) fp16
__device__ float g_ssq[B*DIM];
__device__ float g_ssk[B*DIM];
__device__ float g_G[B*HEADS*C*C];
__device__ float g_A[B*HEADS*C*C];
__device__ __align__(16) __half g_Mh[B*DIM*DIM];  // [b][co][k] fp16

// ================= PTX helpers (compute_103-safe: sm_80+ features) =========
__device__ __forceinline__ uint32_t smem_u32(const void* p) {
    uint32_t a;
    asm("{ .reg .u64 t; cvta.to.shared.u64 t, %1; cvt.u32.u64 %0, t; }"
        : "=r"(a) : "l"(p));
    return a;
}
__device__ __forceinline__ void cpa16(uint32_t saddr, const void* g) {
    asm volatile("cp.async.cg.shared.global [%0], [%1], 16;"
                 :: "r"(saddr), "l"(g) : "memory");
}
#define CP_COMMIT() asm volatile("cp.async.commit_group;" ::: "memory")
#define CP_WAIT1()  asm volatile("cp.async.wait_group 1;" ::: "memory")

__device__ __forceinline__ void ldmA(uint32_t* a, uint32_t addr) {
    asm volatile("ldmatrix.sync.aligned.m8n8.x4.shared.b16 {%0,%1,%2,%3}, [%4];"
        : "=r"(a[0]), "=r"(a[1]), "=r"(a[2]), "=r"(a[3]) : "r"(addr));
}
__device__ __forceinline__ void ldmBt4(uint32_t* bf, uint32_t addr) {
    asm volatile("ldmatrix.sync.aligned.m8n8.x4.trans.shared.b16 {%0,%1,%2,%3}, [%4];"
        : "=r"(bf[0]), "=r"(bf[1]), "=r"(bf[2]), "=r"(bf[3]) : "r"(addr));
}
__device__ __forceinline__ void mma16816(float* c, const uint32_t* a, const uint32_t* bf) {
    asm volatile("mma.sync.aligned.m16n8k16.row.col.f32.f16.f16.f32 "
        "{%0,%1,%2,%3}, {%4,%5,%6,%7}, {%8,%9}, {%0,%1,%2,%3};"
        : "+f"(c[0]), "+f"(c[1]), "+f"(c[2]), "+f"(c[3])
        : "r"(a[0]), "r"(a[1]), "r"(a[2]), "r"(a[3]), "r"(bf[0]), "r"(bf[1]));
}

// ---------------- zero accumulators ----------------------------------------
__global__ void zero_k() {
    int i = blockIdx.x * blockDim.x + threadIdx.x;
    if (i < B*DIM) { g_ssq[i] = 0.f; g_ssk[i] = 0.f; }
    if (i < B*HEADS*C*C) g_G[i] = 0.f;
}

// ---------------- fused depthwise 3x3 convs, sliding-window rows -----------
__device__ __forceinline__ uint32_t pack_h2(float a, float b) {
    __half2 t(__float2half(a), __float2half(b));
    return *reinterpret_cast<uint32_t*>(&t);
}
__global__ void __launch_bounds__(256) dwconv_all(
    const float* __restrict__ qf, const float* __restrict__ kf,
    const float* __restrict__ vf, const float* __restrict__ wq,
    const float* __restrict__ wk, const float* __restrict__ wv)
{
    int which = blockIdx.z;
    const float* in = (which == 0) ? qf : (which == 1) ? kf : vf;
    const float* w  = (which == 0) ? wq : (which == 1) ? wk : wv;
    int bc  = blockIdx.y;
    int c   = bc % DIM;
    int wid = threadIdx.x >> 5, lid = threadIdx.x & 31;
    int y0  = wid * 16;
    int x   = lid * 4;
    const float* ip = in + (size_t)bc * HW;

    float wv9[9];
#pragma unroll
    for (int i = 0; i < 9; i++) wv9[i] = w[c*9 + i];

    float4 mP, mC, mN;
    float lP, rP, lC, rC, lN, rN;

    auto loadrow = [&](int yy, float4& m, float& l, float& r) {
        if ((unsigned)yy < (unsigned)IMG) m = *(const float4*)(ip + yy*IMG + x);
        else m = make_float4(0.f, 0.f, 0.f, 0.f);
        l = __shfl_up_sync(0xffffffffu, m.w, 1);
        r = __shfl_down_sync(0xffffffffu, m.x, 1);
        if (lid == 0)  l = 0.f;
        if (lid == 31) r = 0.f;
    };

    loadrow(y0 - 1, mP, lP, rP);
    loadrow(y0,     mC, lC, rC);

    float ssum = 0.f;
#pragma unroll 4
    for (int yy = 0; yy < 16; yy++) {
        loadrow(y0 + yy + 1, mN, lN, rN);

        float a0 = wv9[0]*lP   + wv9[1]*mP.x + wv9[2]*mP.y
                 + wv9[3]*lC   + wv9[4]*mC.x + wv9[5]*mC.y
                 + wv9[6]*lN   + wv9[7]*mN.x + wv9[8]*mN.y;
        float a1 = wv9[0]*mP.x + wv9[1]*mP.y + wv9[2]*mP.z
                 + wv9[3]*mC.x + wv9[4]*mC.y + wv9[5]*mC.z
                 + wv9[6]*mN.x + wv9[7]*mN.y + wv9[8]*mN.z;
        float a2 = wv9[0]*mP.y + wv9[1]*mP.z + wv9[2]*mP.w
                 + wv9[3]*mC.y + wv9[4]*mC.z + wv9[5]*mC.w
                 + wv9[6]*mN.y + wv9[7]*mN.z + wv9[8]*mN.w;
        float a3 = wv9[0]*mP.z + wv9[1]*mP.w + wv9[2]*rP
                 + wv9[3]*mC.z + wv9[4]*mC.w + wv9[5]*rC
                 + wv9[6]*mN.z + wv9[7]*mN.w + wv9[8]*rN;

        size_t po = (size_t)bc*HW + (y0 + yy)*IMG + x;
        if (which == 2) {
            uint2 uh;
            uh.x = pack_h2(a0, a1); uh.y = pack_h2(a2, a3);
            *(uint2*)&g_vh[po] = uh;
        } else {
            float h0 = __half2float(__float2half(a0));
            float h1 = __half2float(__float2half(a1));
            float h2 = __half2float(__float2half(a2));
            float h3 = __half2float(__float2half(a3));
            uint2 uh, ul;
            uh.x = pack_h2(a0, a1); uh.y = pack_h2(a2, a3);
            ul.x = pack_h2(a0 - h0, a1 - h1); ul.y = pack_h2(a2 - h2, a3 - h3);
            __half* oh = (which == 0) ? g_qh : g_kh;
            __half* ol = (which == 0) ? g_ql : g_kl;
            *(uint2*)&oh[po] = uh;
            *(uint2*)&ol[po] = ul;
            ssum += a0*a0 + a1*a1 + a2*a2 + a3*a3;
        }
        mP = mC; lP = lC; rP = rC;
        mC = mN; lC = lN; rC = rN;
    }

    if (which < 2) {
#pragma unroll
        for (int off = 16; off > 0; off >>= 1)
            ssum += __shfl_xor_sync(0xffffffffu, ssum, off);
        if (lid == 0) {
            float* ssq = (which == 0) ? g_ssq : g_ssk;
            atomicAdd(&ssq[bc], ssum);
        }
    }
}

// ---------------- G = Q @ K^T via tensor cores, fp16 2-term split ----------
// Per (b,h): 48x48 output, K = 16384. Grid (QK_SPLITS, B*HEADS), 8 warps.
// Warp handles a 64-px K-chunk: 4 iterations of k16. Fragments loaded
// directly from gmem (layout matches mma.m16n8k16 row.col). fp32 accum,
// REDG to g_G. Dropped QloKlo term: error ~2^-22, rank-safe.
__global__ void __launch_bounds__(256) gemm_qk_tc()
{
    int bh   = blockIdx.y;
    int warp = threadIdx.x >> 5, lid = threadIdx.x & 31;
    int g    = lid >> 2, q4 = lid & 3;
    size_t base = (size_t)bh * C * HW;     // channel block start
    const __half* qh = g_qh + base;
    const __half* ql = g_ql + base;
    const __half* kh = g_kh + base;
    const __half* kl = g_kl + base;
    int p0 = blockIdx.x * 512 + warp * 64;

    float acc[3][6][4];
#pragma unroll
    for (int mt = 0; mt < 3; mt++)
#pragma unroll
        for (int nt = 0; nt < 6; nt++)
#pragma unroll
            for (int i = 0; i < 4; i++) acc[mt][nt][i] = 0.f;

#pragma unroll
    for (int it = 0; it < 4; it++) {
        int k0 = p0 + it*16;
        uint32_t bhf[6][2], blf[6][2];
#pragma unroll
        for (int nt = 0; nt < 6; nt++) {
            const __half* kr = kh + (size_t)(nt*8 + g)*HW + k0 + q4*2;
            const __half* lr = kl + (size_t)(nt*8 + g)*HW + k0 + q4*2;
            bhf[nt][0] = *(const uint32_t*)kr;
            bhf[nt][1] = *(const uint32_t*)(kr + 8);
            blf[nt][0] = *(const uint32_t*)lr;
            blf[nt][1] = *(const uint32_t*)(lr + 8);
        }
#pragma unroll
        for (int mt = 0; mt < 3; mt++) {
            const __half* qr = qh + (size_t)(mt*16 + g)*HW + k0 + q4*2;
            const __half* sr = ql + (size_t)(mt*16 + g)*HW + k0 + q4*2;
            uint32_t ah[4], al[4];
            ah[0] = *(const uint32_t*)qr;
            ah[1] = *(const uint32_t*)(qr + 8*HW);
            ah[2] = *(const uint32_t*)(qr + 8);
            ah[3] = *(const uint32_t*)(qr + 8*HW + 8);
            al[0] = *(const uint32_t*)sr;
            al[1] = *(const uint32_t*)(sr + 8*HW);
            al[2] = *(const uint32_t*)(sr + 8);
            al[3] = *(const uint32_t*)(sr + 8*HW + 8);
#pragma unroll
            for (int nt = 0; nt < 6; nt++) {
                mma16816(acc[mt][nt], ah, bhf[nt]);
                mma16816(acc[mt][nt], ah, blf[nt]);
                mma16816(acc[mt][nt], al, bhf[nt]);
            }
        }
    }

    float* Gb = &g_G[bh * C * C];
#pragma unroll
    for (int mt = 0; mt < 3; mt++) {
        int row = mt*16 + g;
#pragma unroll
        for (int nt = 0; nt < 6; nt++) {
            int col = nt*8 + q4*2;
            atomicAdd(&Gb[row*C + col],        acc[mt][nt][0]);
            atomicAdd(&Gb[row*C + col + 1],    acc[mt][nt][1]);
            atomicAdd(&Gb[(row+8)*C + col],    acc[mt][nt][2]);
            atomicAdd(&Gb[(row+8)*C + col + 1],acc[mt][nt][3]);
        }
    }
}

// ---------------- rowcomb: warp-per-row, rank-based ------------------------
__global__ void __launch_bounds__(256) rowcomb(const float* __restrict__ temp,
                                               const float* __restrict__ attw)
{
    __shared__ float sv[8][48];
    int wid = threadIdx.x >> 5, lid = threadIdx.x & 31;
    int row = blockIdx.x * 8 + wid;
    int b   = row / (HEADS*C);
    int rem = row % (HEADS*C);
    int hd  = rem / C, c = rem % C;

    float inq = 1.f / fmaxf(sqrtf(g_ssq[b*DIM + hd*C + c]), 1e-12f);
    float t   = temp[hd];
    const float* Gr = &g_G[((b*HEADS + hd)*C + c) * C];

    float v0, v1 = -1e30f;
    {
        float ink = 1.f / fmaxf(sqrtf(g_ssk[b*DIM + hd*C + lid]), 1e-12f);
        v0 = Gr[lid] * inq * ink * t;
        sv[wid][lid] = v0;
        if (lid < 16) {
            int d = lid + 32;
            float ink2 = 1.f / fmaxf(sqrtf(g_ssk[b*DIM + hd*C + d]), 1e-12f);
            v1 = Gr[d] * inq * ink2 * t;
            sv[wid][d] = v1;
        }
    }
    __syncwarp();

    float m = fmaxf(v0, v1);
#pragma unroll
    for (int off = 16; off > 0; off >>= 1)
        m = fmaxf(m, __shfl_xor_sync(0xffffffffu, m, off));

    int r0 = 0, r1 = 0;
#pragma unroll 8
    for (int j = 0; j < C; j++) {
        float vj = sv[wid][j];
        r0 += (vj > v0) || (vj == v0 && j < lid);
        if (lid < 16) r1 += (vj > v1) || (vj == v1 && j < lid + 32);
    }
    float e0 = expf(v0 - m);
    float e1 = (lid < 16) ? expf(v1 - m) : 0.f;

    const int kl[4] = {C/2, C*2/3, C*3/4, C*4/5};
    float ds[4];
#pragma unroll
    for (int i = 0; i < 4; i++)
        ds[i] = ((r0 < kl[i]) ? e0 : 0.f) + ((lid < 16 && r1 < kl[i]) ? e1 : 0.f);
#pragma unroll
    for (int off = 16; off > 0; off >>= 1) {
#pragma unroll
        for (int i = 0; i < 4; i++)
            ds[i] += __shfl_xor_sync(0xffffffffu, ds[i], off);
    }

    float cf0 = 0.f, cf1 = 0.f;
#pragma unroll
    for (int i = 0; i < 4; i++) {
        float wdi = attw[i] / ds[i];
        if (r0 < kl[i]) cf0 += wdi;
        if (r1 < kl[i]) cf1 += wdi;
    }

    float* Ar = &g_A[((b*HEADS + hd)*C + c) * C];
    Ar[lid] = e0 * cf0;
    if (lid < 16) Ar[lid + 32] = e1 * cf1;
}

// ---------------- M[b] = Wproj @ blockdiag(A[b]) -> fp16 -------------------
__global__ void buildM(const float* __restrict__ wproj)
{
    int idx = blockIdx.x * blockDim.x + threadIdx.x;
    if (idx >= B*DIM*DIM) return;
    int b  = idx / (DIM*DIM);
    int r  = idx % (DIM*DIM);
    int co = r / DIM;
    int g  = r % DIM;
    int hh = g / C, dl = g % C;

    const float* wp = wproj + co*DIM + hh*C;
    const float* Ac = &g_A[((b*HEADS + hh)*C) * C + dl];
    float acc = 0.f;
#pragma unroll
    for (int cc = 0; cc < C; cc++) acc += wp[cc] * Ac[cc*C];
    g_Mh[idx] = __float2half(acc);
}

// ---------------- final GEMM: M_fp16 @ V_fp16, single pass -----------------
#define AST_B 80
#define BST_B 272
#define A_STG (128*AST_B)      // 10240
#define B_STG (32*BST_B)       // 8704
#define OFF_A 0
#define OFF_B (2*A_STG)        // 20480
#define FG_SMEM (2*A_STG + 2*B_STG)   // 37888
#define NKC 12

__global__ void __launch_bounds__(256, 2) finalgemm(float* __restrict__ y)
{
    extern __shared__ char smem[];
    uint32_t sb = smem_u32(smem);
    int tid = threadIdx.x, wid = tid >> 5, lid = tid & 31;
    int b   = blockIdx.z;
    int co0 = blockIdx.y * 128;
    int p0  = blockIdx.x * 128;
    int wm  = (wid & 1) * 64;
    int wn  = (wid >> 1) * 32;

    const __half* Mh = g_Mh + (size_t)b * DIM * DIM;
    const __half* Vh = g_vh + (size_t)b * DIM * HW;

    float acc[4][4][4];
#pragma unroll
    for (int mt = 0; mt < 4; mt++)
#pragma unroll
        for (int nt = 0; nt < 4; nt++)
#pragma unroll
            for (int i = 0; i < 4; i++) acc[mt][nt][i] = 0.f;

    auto load_chunk = [&](int kc, int st) {
        int k0 = kc * 32;
#pragma unroll
        for (int i = tid; i < 512; i += 256) {
            int r = i >> 2, cc = i & 3;
            size_t go = (size_t)(co0 + r)*DIM + k0 + cc*8;
            uint32_t so = r*AST_B + cc*16;
            cpa16(sb + OFF_A + st*A_STG + so, Mh + go);
        }
#pragma unroll
        for (int i = tid; i < 512; i += 256) {
            int r = i >> 4, cc = i & 15;
            size_t go = (size_t)(k0 + r)*HW + p0 + cc*8;
            uint32_t so = r*BST_B + cc*16;
            cpa16(sb + OFF_B + st*B_STG + so, Vh + go);
        }
    };

    load_chunk(0, 0);
    CP_COMMIT();

    for (int kc = 0; kc < NKC; kc++) {
        int st = kc & 1;
        if (kc + 1 < NKC) load_chunk(kc + 1, (kc + 1) & 1);
        CP_COMMIT();
        CP_WAIT1();
        __syncthreads();

        uint32_t aA = sb + OFF_A + st*A_STG + (wm + (lid & 15))*AST_B + (lid >> 4)*16;
        uint32_t aB = sb + OFF_B + st*B_STG + (lid & 15)*BST_B + wn*2 + (lid >> 4)*16;

#pragma unroll
        for (int ks = 0; ks < 2; ks++) {
            uint32_t Ah[4][4];
#pragma unroll
            for (int mt = 0; mt < 4; mt++)
                ldmA(Ah[mt], aA + mt*16*AST_B + ks*32);
#pragma unroll
            for (int nt0 = 0; nt0 < 4; nt0 += 2) {
                uint32_t Bh[4];
                ldmBt4(Bh, aB + ks*16*BST_B + nt0*16);
#pragma unroll
                for (int q = 0; q < 2; q++)
#pragma unroll
                    for (int mt = 0; mt < 4; mt++)
                        mma16816(acc[mt][nt0+q], Ah[mt], &Bh[q*2]);
            }
        }
        __syncthreads();
    }

    int group = lid >> 2, tg = lid & 3;
#pragma unroll
    for (int mt = 0; mt < 4; mt++) {
        int row0 = co0 + wm + mt*16 + group;
#pragma unroll
        for (int nt = 0; nt < 4; nt++) {
            int col = p0 + wn + nt*8 + tg*2;
            size_t o0 = ((size_t)(b*DIM + row0))     * HW + col;
            size_t o1 = ((size_t)(b*DIM + row0 + 8)) * HW + col;
            *(float2*)&y[o0] = make_float2(acc[mt][nt][0], acc[mt][nt][1]);
            *(float2*)&y[o1] = make_float2(acc[mt][nt][2], acc[mt][nt][3]);
        }
    }
}

// ---------------- launch ----------------------------------------------------
extern "C" void kernel_launch(void* const* d_in, const int* in_sizes, int n_in,
                              void* d_out, int out_size)
{
    const float* k_fea = (const float*)d_in[0];
    const float* v_fea = (const float*)d_in[1];
    const float* q_fea = (const float*)d_in[2];
    const float* wq    = (const float*)d_in[3];
    const float* wk    = (const float*)d_in[4];
    const float* wv    = (const float*)d_in[5];
    const float* wproj = (const float*)d_in[6];
    const float* temp  = (const float*)d_in[7];
    const float* attw  = (const float*)d_in[8];
    float* y = (float*)d_out;

    static int smem_set = 0;
    if (!smem_set) {
        cudaFuncSetAttribute(finalgemm, cudaFuncAttributeMaxDynamicSharedMemorySize,
                             FG_SMEM);
        smem_set = 1;
    }

    zero_k<<<(B*HEADS*C*C + 255)/256, 256>>>();

    dwconv_all<<<dim3(1, B*DIM, 3), 256>>>(q_fea, k_fea, v_fea, wq, wk, wv);

    gemm_qk_tc<<<dim3(QK_SPLITS, B*HEADS), 256>>>();

    rowcomb<<<(B*HEADS*C)/8, 256>>>(temp, attw);

    buildM<<<(B*DIM*DIM + 255)/256, 256>>>(wproj);

    finalgemm<<<dim3(HW/128, DIM/128, B), 256, FG_SMEM>>>(y);
}

// round 8
// speedup vs baseline: 10.6031x; 1.2550x over previous
#include <cuda_runtime.h>
#include <cuda_fp16.h>
#include <cstdint>
#include <math.h>

#define B 2
#define DIM 384
#define HEADS 8
#define C 48
#define IMG 128
#define HW (IMG*IMG)        // 16384

// ---------------- scratch (static device globals; no allocations) ----------
__device__ __align__(16) __half g_qh[B*DIM*HW];   // dwconv(q) fp16 hi
__device__ __align__(16) __half g_ql[B*DIM*HW];   // dwconv(q) fp16 lo
__device__ __align__(16) __half g_kh[B*DIM*HW];   // dwconv(k) fp16 hi
__device__ __align__(16) __half g_kl[B*DIM*HW];   // dwconv(k) fp16 lo
__device__ __align__(16) __half g_vh[B*DIM*HW];   // dwconv(v) fp16
__device__ float g_ssq[B*DIM];
__device__ float g_ssk[B*DIM];
__device__ float g_G[B*HEADS*C*C];
__device__ float g_A[B*HEADS*C*C];
__device__ __align__(16) __half g_Mh[B*DIM*DIM];  // [b][co][k] fp16

// ================= PTX helpers (compute_103-safe: sm_80+ features) =========
__device__ __forceinline__ uint32_t smem_u32(const void* p) {
    uint32_t a;
    asm("{ .reg .u64 t; cvta.to.shared.u64 t, %1; cvt.u32.u64 %0, t; }"
        : "=r"(a) : "l"(p));
    return a;
}
__device__ __forceinline__ void cpa16(uint32_t saddr, const void* g) {
    asm volatile("cp.async.cg.shared.global [%0], [%1], 16;"
                 :: "r"(saddr), "l"(g) : "memory");
}
#define CP_COMMIT() asm volatile("cp.async.commit_group;" ::: "memory")
#define CP_WAIT1()  asm volatile("cp.async.wait_group 1;" ::: "memory")
#define CP_WAIT2()  asm volatile("cp.async.wait_group 2;" ::: "memory")

__device__ __forceinline__ void ldmA(uint32_t* a, uint32_t addr) {
    asm volatile("ldmatrix.sync.aligned.m8n8.x4.shared.b16 {%0,%1,%2,%3}, [%4];"
        : "=r"(a[0]), "=r"(a[1]), "=r"(a[2]), "=r"(a[3]) : "r"(addr));
}
__device__ __forceinline__ void ldmBt4(uint32_t* bf, uint32_t addr) {
    asm volatile("ldmatrix.sync.aligned.m8n8.x4.trans.shared.b16 {%0,%1,%2,%3}, [%4];"
        : "=r"(bf[0]), "=r"(bf[1]), "=r"(bf[2]), "=r"(bf[3]) : "r"(addr));
}
__device__ __forceinline__ void mma16816(float* c, const uint32_t* a, const uint32_t* bf) {
    asm volatile("mma.sync.aligned.m16n8k16.row.col.f32.f16.f16.f32 "
        "{%0,%1,%2,%3}, {%4,%5,%6,%7}, {%8,%9}, {%0,%1,%2,%3};"
        : "+f"(c[0]), "+f"(c[1]), "+f"(c[2]), "+f"(c[3])
        : "r"(a[0]), "r"(a[1]), "r"(a[2]), "r"(a[3]), "r"(bf[0]), "r"(bf[1]));
}

// ---------------- zero accumulators ----------------------------------------
__global__ void zero_k() {
    int i = blockIdx.x * blockDim.x + threadIdx.x;
    if (i < B*DIM) { g_ssq[i] = 0.f; g_ssk[i] = 0.f; }
    if (i < B*HEADS*C*C) g_G[i] = 0.f;
}

// ---------------- fused depthwise 3x3 convs, sliding-window rows -----------
__device__ __forceinline__ uint32_t pack_h2(float a, float b) {
    __half2 t(__float2half(a), __float2half(b));
    return *reinterpret_cast<uint32_t*>(&t);
}
__global__ void __launch_bounds__(256) dwconv_all(
    const float* __restrict__ qf, const float* __restrict__ kf,
    const float* __restrict__ vf, const float* __restrict__ wq,
    const float* __restrict__ wk, const float* __restrict__ wv)
{
    int which = blockIdx.z;
    const float* in = (which == 0) ? qf : (which == 1) ? kf : vf;
    const float* w  = (which == 0) ? wq : (which == 1) ? wk : wv;
    int bc  = blockIdx.y;
    int c   = bc % DIM;
    int wid = threadIdx.x >> 5, lid = threadIdx.x & 31;
    int y0  = wid * 16;
    int x   = lid * 4;
    const float* ip = in + (size_t)bc * HW;

    float wv9[9];
#pragma unroll
    for (int i = 0; i < 9; i++) wv9[i] = w[c*9 + i];

    float4 mP, mC, mN;
    float lP, rP, lC, rC, lN, rN;

    auto loadrow = [&](int yy, float4& m, float& l, float& r) {
        if ((unsigned)yy < (unsigned)IMG) m = *(const float4*)(ip + yy*IMG + x);
        else m = make_float4(0.f, 0.f, 0.f, 0.f);
        l = __shfl_up_sync(0xffffffffu, m.w, 1);
        r = __shfl_down_sync(0xffffffffu, m.x, 1);
        if (lid == 0)  l = 0.f;
        if (lid == 31) r = 0.f;
    };

    loadrow(y0 - 1, mP, lP, rP);
    loadrow(y0,     mC, lC, rC);

    float ssum = 0.f;
#pragma unroll 4
    for (int yy = 0; yy < 16; yy++) {
        loadrow(y0 + yy + 1, mN, lN, rN);

        float a0 = wv9[0]*lP   + wv9[1]*mP.x + wv9[2]*mP.y
                 + wv9[3]*lC   + wv9[4]*mC.x + wv9[5]*mC.y
                 + wv9[6]*lN   + wv9[7]*mN.x + wv9[8]*mN.y;
        float a1 = wv9[0]*mP.x + wv9[1]*mP.y + wv9[2]*mP.z
                 + wv9[3]*mC.x + wv9[4]*mC.y + wv9[5]*mC.z
                 + wv9[6]*mN.x + wv9[7]*mN.y + wv9[8]*mN.z;
        float a2 = wv9[0]*mP.y + wv9[1]*mP.z + wv9[2]*mP.w
                 + wv9[3]*mC.y + wv9[4]*mC.z + wv9[5]*mC.w
                 + wv9[6]*mN.y + wv9[7]*mN.z + wv9[8]*mN.w;
        float a3 = wv9[0]*mP.z + wv9[1]*mP.w + wv9[2]*rP
                 + wv9[3]*mC.z + wv9[4]*mC.w + wv9[5]*rC
                 + wv9[6]*mN.z + wv9[7]*mN.w + wv9[8]*rN;

        size_t po = (size_t)bc*HW + (y0 + yy)*IMG + x;
        if (which == 2) {
            uint2 uh;
            uh.x = pack_h2(a0, a1); uh.y = pack_h2(a2, a3);
            *(uint2*)&g_vh[po] = uh;
        } else {
            float h0 = __half2float(__float2half(a0));
            float h1 = __half2float(__float2half(a1));
            float h2 = __half2float(__float2half(a2));
            float h3 = __half2float(__float2half(a3));
            uint2 uh, ul;
            uh.x = pack_h2(a0, a1); uh.y = pack_h2(a2, a3);
            ul.x = pack_h2(a0 - h0, a1 - h1); ul.y = pack_h2(a2 - h2, a3 - h3);
            __half* oh = (which == 0) ? g_qh : g_kh;
            __half* ol = (which == 0) ? g_ql : g_kl;
            *(uint2*)&oh[po] = uh;
            *(uint2*)&ol[po] = ul;
            ssum += a0*a0 + a1*a1 + a2*a2 + a3*a3;
        }
        mP = mC; lP = lC; rP = rC;
        mC = mN; lC = lN; rC = rN;
    }

    if (which < 2) {
#pragma unroll
        for (int off = 16; off > 0; off >>= 1)
            ssum += __shfl_xor_sync(0xffffffffu, ssum, off);
        if (lid == 0) {
            float* ssq = (which == 0) ? g_ssq : g_ssk;
            atomicAdd(&ssq[bc], ssum);
        }
    }
}

// ---------------- G = Q @ K^T via tensor cores, smem-staged ----------------
// Grid (32, B*HEADS), 128 threads (4 warps). Per CTA: 512-px K-chunk in 8
// double-buffered 64-px waves. Each warp owns a k16 slice of each wave and
// the FULL 48x48 tile (3-term fp16 split, fp32 accum). Epilogue: smem tile
// reduction across warps, then one atomicAdd pass (32 adds/address total).
#define QK_SPLITS 32
#define QK_CHUNK (HW/QK_SPLITS)   // 512
#define QROW_B 144                // 64 fp16 = 128B + 16B pad (LDSM conflict-free)
#define QT_BYTES (C*QROW_B)       // 6912
#define QSTG (4*QT_BYTES)         // 27648 (qhi,qlo,khi,klo)
#define QK_SMEM (2*QSTG)          // 55296

__global__ void __launch_bounds__(128) gemm_qk_tc()
{
    extern __shared__ char smem[];
    uint32_t sb = smem_u32(smem);
    int tid = threadIdx.x, w = tid >> 5, lid = tid & 31;
    int bh  = blockIdx.y;
    size_t chbase = (size_t)bh * C * HW;

    float acc[3][6][4];
#pragma unroll
    for (int mt = 0; mt < 3; mt++)
#pragma unroll
        for (int nt = 0; nt < 6; nt++)
#pragma unroll
            for (int i = 0; i < 4; i++) acc[mt][nt][i] = 0.f;

    auto load_wave = [&](int wv, int st) {
        int px0 = blockIdx.x * QK_CHUNK + wv * 64;
#pragma unroll
        for (int t = 0; t < 4; t++) {
            const __half* src =
                ((t == 0) ? g_qh : (t == 1) ? g_ql : (t == 2) ? g_kh : g_kl) + chbase;
#pragma unroll
            for (int j = 0; j < 3; j++) {
                int i = tid + j*128;      // 0..383
                int r = i >> 3, ck = i & 7;
                cpa16(sb + st*QSTG + t*QT_BYTES + r*QROW_B + ck*16,
                      src + (size_t)r*HW + px0 + ck*8);
            }
        }
    };

    load_wave(0, 0);
    CP_COMMIT();

    for (int wv = 0; wv < 8; wv++) {
        if (wv + 1 < 8) load_wave(wv + 1, (wv + 1) & 1);
        CP_COMMIT();
        CP_WAIT1();
        __syncthreads();

        uint32_t base = sb + (wv & 1)*QSTG + w*32;   // warp's k16 slice
        uint32_t ah[3][4], al[3][4];
#pragma unroll
        for (int mt = 0; mt < 3; mt++) {
            uint32_t ao = base + (uint32_t)(mt*16 + (lid & 15))*QROW_B + ((lid >> 4) << 4);
            ldmA(ah[mt], ao);                 // q hi
            ldmA(al[mt], ao + QT_BYTES);      // q lo
        }
#pragma unroll
        for (int ntp = 0; ntp < 3; ntp++) {
            uint32_t bo = base + 2*QT_BYTES
                        + (uint32_t)(ntp*16 + ((lid >> 4) << 3) + (lid & 7))*QROW_B
                        + (((lid >> 3) & 1) << 4);
            uint32_t bh4[4], bl4[4];
            ldmA(bh4, bo);                    // k hi (non-trans x4: two n8 tiles)
            ldmA(bl4, bo + QT_BYTES);         // k lo
#pragma unroll
            for (int q = 0; q < 2; q++)
#pragma unroll
                for (int mt = 0; mt < 3; mt++) {
                    mma16816(acc[mt][ntp*2+q], ah[mt], &bh4[q*2]);
                    mma16816(acc[mt][ntp*2+q], ah[mt], &bl4[q*2]);
                    mma16816(acc[mt][ntp*2+q], al[mt], &bh4[q*2]);
                }
        }
        __syncthreads();
    }

    // ---- reduce 4 warps' tiles in smem (serialized rounds), then atomics ----
    float* sred = (float*)smem;        // 48 x 49 floats, aliases stage memory
    int grp = lid >> 2, tg = lid & 3;
#pragma unroll
    for (int rw = 0; rw < 4; rw++) {
        if (w == rw) {
#pragma unroll
            for (int mt = 0; mt < 3; mt++)
#pragma unroll
                for (int nt = 0; nt < 6; nt++)
#pragma unroll
                    for (int i = 0; i < 4; i++) {
                        int row = mt*16 + grp + (i >> 1)*8;
                        int col = nt*8 + tg*2 + (i & 1);
                        if (rw == 0) sred[row*49 + col] = acc[mt][nt][i];
                        else         sred[row*49 + col] += acc[mt][nt][i];
                    }
        }
        __syncthreads();
    }
    float* Gb = &g_G[bh * C * C];
    for (int i = tid; i < C*C; i += 128) {
        int row = i / C, col = i % C;
        atomicAdd(&Gb[i], sred[row*49 + col]);
    }
}

// ---------------- rowcomb: warp-per-row, rank-based ------------------------
__global__ void __launch_bounds__(256) rowcomb(const float* __restrict__ temp,
                                               const float* __restrict__ attw)
{
    __shared__ float sv[8][48];
    int wid = threadIdx.x >> 5, lid = threadIdx.x & 31;
    int row = blockIdx.x * 8 + wid;
    int b   = row / (HEADS*C);
    int rem = row % (HEADS*C);
    int hd  = rem / C, c = rem % C;

    float inq = 1.f / fmaxf(sqrtf(g_ssq[b*DIM + hd*C + c]), 1e-12f);
    float t   = temp[hd];
    const float* Gr = &g_G[((b*HEADS + hd)*C + c) * C];

    float v0, v1 = -1e30f;
    {
        float ink = 1.f / fmaxf(sqrtf(g_ssk[b*DIM + hd*C + lid]), 1e-12f);
        v0 = Gr[lid] * inq * ink * t;
        sv[wid][lid] = v0;
        if (lid < 16) {
            int d = lid + 32;
            float ink2 = 1.f / fmaxf(sqrtf(g_ssk[b*DIM + hd*C + d]), 1e-12f);
            v1 = Gr[d] * inq * ink2 * t;
            sv[wid][d] = v1;
        }
    }
    __syncwarp();

    float m = fmaxf(v0, v1);
#pragma unroll
    for (int off = 16; off > 0; off >>= 1)
        m = fmaxf(m, __shfl_xor_sync(0xffffffffu, m, off));

    int r0 = 0, r1 = 0;
#pragma unroll 8
    for (int j = 0; j < C; j++) {
        float vj = sv[wid][j];
        r0 += (vj > v0) || (vj == v0 && j < lid);
        if (lid < 16) r1 += (vj > v1) || (vj == v1 && j < lid + 32);
    }
    float e0 = expf(v0 - m);
    float e1 = (lid < 16) ? expf(v1 - m) : 0.f;

    const int kl[4] = {C/2, C*2/3, C*3/4, C*4/5};
    float ds[4];
#pragma unroll
    for (int i = 0; i < 4; i++)
        ds[i] = ((r0 < kl[i]) ? e0 : 0.f) + ((lid < 16 && r1 < kl[i]) ? e1 : 0.f);
#pragma unroll
    for (int off = 16; off > 0; off >>= 1) {
#pragma unroll
        for (int i = 0; i < 4; i++)
            ds[i] += __shfl_xor_sync(0xffffffffu, ds[i], off);
    }

    float cf0 = 0.f, cf1 = 0.f;
#pragma unroll
    for (int i = 0; i < 4; i++) {
        float wdi = attw[i] / ds[i];
        if (r0 < kl[i]) cf0 += wdi;
        if (r1 < kl[i]) cf1 += wdi;
    }

    float* Ar = &g_A[((b*HEADS + hd)*C + c) * C];
    Ar[lid] = e0 * cf0;
    if (lid < 16) Ar[lid + 32] = e1 * cf1;
}

// ---------------- M[b] = Wproj @ blockdiag(A[b]) -> fp16 -------------------
__global__ void buildM(const float* __restrict__ wproj)
{
    int idx = blockIdx.x * blockDim.x + threadIdx.x;
    if (idx >= B*DIM*DIM) return;
    int b  = idx / (DIM*DIM);
    int r  = idx % (DIM*DIM);
    int co = r / DIM;
    int g  = r % DIM;
    int hh = g / C, dl = g % C;

    const float* wp = wproj + co*DIM + hh*C;
    const float* Ac = &g_A[((b*HEADS + hh)*C) * C + dl];
    float acc = 0.f;
#pragma unroll
    for (int cc = 0; cc < C; cc++) acc += wp[cc] * Ac[cc*C];
    g_Mh[idx] = __float2half(acc);
}

// ---------------- final GEMM: M_fp16 @ V_fp16, 4-stage pipeline ------------
#define AST_B 80
#define BST_B 272
#define A_STG (128*AST_B)      // 10240
#define B_STG (32*BST_B)       // 8704
#define STG_B (A_STG + B_STG)  // 18944 per stage
#define FG_SMEM (4*STG_B)      // 75776
#define NKC 12

__global__ void __launch_bounds__(256, 2) finalgemm(float* __restrict__ y)
{
    extern __shared__ char smem[];
    uint32_t sb = smem_u32(smem);
    int tid = threadIdx.x, wid = tid >> 5, lid = tid & 31;
    int b   = blockIdx.z;
    int co0 = blockIdx.y * 128;
    int p0  = blockIdx.x * 128;
    int wm  = (wid & 1) * 64;
    int wn  = (wid >> 1) * 32;

    const __half* Mh = g_Mh + (size_t)b * DIM * DIM;
    const __half* Vh = g_vh + (size_t)b * DIM * HW;

    float acc[4][4][4];
#pragma unroll
    for (int mt = 0; mt < 4; mt++)
#pragma unroll
        for (int nt = 0; nt < 4; nt++)
#pragma unroll
            for (int i = 0; i < 4; i++) acc[mt][nt][i] = 0.f;

    auto load_chunk = [&](int kc, int st) {
        int k0 = kc * 32;
        uint32_t sbase = sb + st*STG_B;
#pragma unroll
        for (int i = tid; i < 512; i += 256) {
            int r = i >> 2, cc = i & 3;
            size_t go = (size_t)(co0 + r)*DIM + k0 + cc*8;
            cpa16(sbase + r*AST_B + cc*16, Mh + go);
        }
#pragma unroll
        for (int i = tid; i < 512; i += 256) {
            int r = i >> 4, cc = i & 15;
            size_t go = (size_t)(k0 + r)*HW + p0 + cc*8;
            cpa16(sbase + A_STG + r*BST_B + cc*16, Vh + go);
        }
    };

    load_chunk(0, 0);
    CP_COMMIT();
    load_chunk(1, 1);
    CP_COMMIT();

    for (int kc = 0; kc < NKC; kc++) {
        if (kc + 2 < NKC) load_chunk(kc + 2, (kc + 2) & 3);
        CP_COMMIT();
        CP_WAIT2();
        __syncthreads();

        uint32_t sbase = sb + (kc & 3)*STG_B;
        uint32_t aA = sbase + (wm + (lid & 15))*AST_B + ((lid >> 4) << 4);
        uint32_t aB = sbase + A_STG + (lid & 15)*BST_B + wn*2 + ((lid >> 4) << 4);

#pragma unroll
        for (int ks = 0; ks < 2; ks++) {
            uint32_t Ah[4][4];
#pragma unroll
            for (int mt = 0; mt < 4; mt++)
                ldmA(Ah[mt], aA + mt*16*AST_B + ks*32);
#pragma unroll
            for (int nt0 = 0; nt0 < 4; nt0 += 2) {
                uint32_t Bh[4];
                ldmBt4(Bh, aB + ks*16*BST_B + nt0*16);
#pragma unroll
                for (int q = 0; q < 2; q++)
#pragma unroll
                    for (int mt = 0; mt < 4; mt++)
                        mma16816(acc[mt][nt0+q], Ah[mt], &Bh[q*2]);
            }
        }
    }

    __syncthreads();
    int group = lid >> 2, tg = lid & 3;
#pragma unroll
    for (int mt = 0; mt < 4; mt++) {
        int row0 = co0 + wm + mt*16 + group;
#pragma unroll
        for (int nt = 0; nt < 4; nt++) {
            int col = p0 + wn + nt*8 + tg*2;
            size_t o0 = ((size_t)(b*DIM + row0))     * HW + col;
            size_t o1 = ((size_t)(b*DIM + row0 + 8)) * HW + col;
            *(float2*)&y[o0] = make_float2(acc[mt][nt][0], acc[mt][nt][1]);
            *(float2*)&y[o1] = make_float2(acc[mt][nt][2], acc[mt][nt][3]);
        }
    }
}

// ---------------- launch ----------------------------------------------------
extern "C" void kernel_launch(void* const* d_in, const int* in_sizes, int n_in,
                              void* d_out, int out_size)
{
    const float* k_fea = (const float*)d_in[0];
    const float* v_fea = (const float*)d_in[1];
    const float* q_fea = (const float*)d_in[2];
    const float* wq    = (const float*)d_in[3];
    const float* wk    = (const float*)d_in[4];
    const float* wv    = (const float*)d_in[5];
    const float* wproj = (const float*)d_in[6];
    const float* temp  = (const float*)d_in[7];
    const float* attw  = (const float*)d_in[8];
    float* y = (float*)d_out;

    static int smem_set = 0;
    if (!smem_set) {
        cudaFuncSetAttribute(finalgemm, cudaFuncAttributeMaxDynamicSharedMemorySize,
                             FG_SMEM);
        cudaFuncSetAttribute(gemm_qk_tc, cudaFuncAttributeMaxDynamicSharedMemorySize,
                             QK_SMEM);
        smem_set = 1;
    }

    zero_k<<<(B*HEADS*C*C + 255)/256, 256>>>();

    dwconv_all<<<dim3(1, B*DIM, 3), 256>>>(q_fea, k_fea, v_fea, wq, wk, wv);

    gemm_qk_tc<<<dim3(QK_SPLITS, B*HEADS), 128, QK_SMEM>>>();

    rowcomb<<<(B*HEADS*C)/8, 256>>>(temp, attw);

    buildM<<<(B*DIM*DIM + 255)/256, 256>>>(wproj);

    finalgemm<<<dim3(HW/128, DIM/128, B), 256, FG_SMEM>>>(y);
}